// round 10
// baseline (speedup 1.0000x reference)
#include <cuda_runtime.h>
#include <cuda_bf16.h>
#include <math.h>
#include <stdint.h>

// Problem constants
#define BB   4096
#define GG   4096
#define NF2  384               // fused gene+term0 output width (64 terms x 6)
#define OUTC 86
#define EPSB 1e-5f
#define PSLI 64                // max partial-stat slices

// ---------------- scratch (device globals) ---------------------------------
__device__ __align__(16) float g_h0[BB * 384];
__device__ __align__(16) float g_h1[BB * 96];
__device__ __align__(16) float g_h2[BB * 24];
__device__ __align__(16) float g_h3[BB * 6];
__device__ __align__(16) float g_f [BB * 6];
__device__ float g_psum[PSLI * 512];
__device__ float g_psq [PSLI * 512];
__device__ __align__(16) __nv_bfloat16 g_xhi[BB * GG];
__device__ __align__(16) __nv_bfloat16 g_xlo[BB * GG];
__device__ __align__(16) __nv_bfloat16 g_weffhi[NF2 * GG];
__device__ __align__(16) __nv_bfloat16 g_wefflo[NF2 * GG];
__device__ float g_beff[NF2];

// ======================= helpers ===========================================
__device__ __forceinline__ uint32_t smem_u32(const void* p) {
    uint32_t a;
    asm("{ .reg .u64 t; cvta.to.shared.u64 t, %1; cvt.u32.u64 %0, t; }" : "=r"(a) : "l"(p));
    return a;
}
#define CPA16(dst, src) \
    asm volatile("cp.async.cg.shared.global [%0], [%1], 16;" :: "r"(dst), "l"(src))
#define CPA_COMMIT() asm volatile("cp.async.commit_group;" ::: "memory")

#define LDSM4(r, addr) \
    asm volatile("ldmatrix.sync.aligned.m8n8.x4.shared.b16 {%0,%1,%2,%3}, [%4];" \
                 : "=r"((r)[0]), "=r"((r)[1]), "=r"((r)[2]), "=r"((r)[3]) : "r"(addr))

__device__ __forceinline__ void mma_bf16(float* d, const uint32_t* a, const uint32_t* b) {
    asm volatile(
        "mma.sync.aligned.m16n8k16.row.col.f32.bf16.bf16.f32 "
        "{%0,%1,%2,%3}, {%4,%5,%6,%7}, {%8,%9}, {%0,%1,%2,%3};"
        : "+f"(d[0]), "+f"(d[1]), "+f"(d[2]), "+f"(d[3])
        : "r"(a[0]), "r"(a[1]), "r"(a[2]), "r"(a[3]), "r"(b[0]), "r"(b[1]));
}

// ======================= fp32 -> bf16 hi/lo split ==========================
__global__ void __launch_bounds__(256)
split_kernel(const float* __restrict__ src, __nv_bfloat16* __restrict__ hi,
             __nv_bfloat16* __restrict__ lo, int n4) {
    int i = blockIdx.x * blockDim.x + threadIdx.x;
    if (i >= n4) return;
    float4 v = ((const float4*)src)[i];
    __nv_bfloat16 h0 = __float2bfloat16(v.x), h1 = __float2bfloat16(v.y);
    __nv_bfloat16 h2 = __float2bfloat16(v.z), h3 = __float2bfloat16(v.w);
    __nv_bfloat16 l0 = __float2bfloat16(v.x - __bfloat162float(h0));
    __nv_bfloat16 l1 = __float2bfloat16(v.y - __bfloat162float(h1));
    __nv_bfloat16 l2 = __float2bfloat16(v.z - __bfloat162float(h2));
    __nv_bfloat16 l3 = __float2bfloat16(v.w - __bfloat162float(h3));
    ((__nv_bfloat162*)hi)[i * 2 + 0] = __nv_bfloat162{h0, h1};
    ((__nv_bfloat162*)hi)[i * 2 + 1] = __nv_bfloat162{h2, h3};
    ((__nv_bfloat162*)lo)[i * 2 + 0] = __nv_bfloat162{l0, l1};
    ((__nv_bfloat162*)lo)[i * 2 + 1] = __nv_bfloat162{l2, l3};
}

// ======================= W_eff precompute ==================================
__global__ void __launch_bounds__(256)
weff_kernel(const float* __restrict__ geneW, const float* __restrict__ geneb,
            const float* __restrict__ termW, const float* __restrict__ termb,
            __nv_bfloat16* __restrict__ whi, __nv_bfloat16* __restrict__ wlo,
            float* __restrict__ beff) {
    const int t = blockIdx.y;
    __shared__ float tw[144];
    if (threadIdx.x < 144) tw[threadIdx.x] = termW[(size_t)t * 144 + threadIdx.x];
    __syncthreads();
    const int g = blockIdx.x * 256 + threadIdx.x;
    float gw[24];
#pragma unroll
    for (int k = 0; k < 24; k++) gw[k] = geneW[((size_t)t * 24 + k) * GG + g];
#pragma unroll
    for (int h = 0; h < 6; h++) {
        float s = 0.0f;
#pragma unroll
        for (int k = 0; k < 24; k++) s = fmaf(tw[h * 24 + k], gw[k], s);
        __nv_bfloat16 hi = __float2bfloat16(s);
        float lo = s - __bfloat162float(hi);
        whi[((size_t)(t * 6 + h)) * GG + g] = hi;
        wlo[((size_t)(t * 6 + h)) * GG + g] = __float2bfloat16(lo);
    }
    if (blockIdx.x == 0 && threadIdx.x < 6) {
        const int h = threadIdx.x;
        float s = termb[t * 6 + h];
#pragma unroll
        for (int k = 0; k < 24; k++) s = fmaf(tw[h * 24 + k], geneb[t * 24 + k], s);
        beff[t * 6 + h] = s;
    }
}

// ======================= fused bf16 GEMM + tanh + partial BN stats =========
// CTA tile 64x64, 4 warps, KCH=64, 2-stage cp.async, 3 CTAs/SM.
// Epilogue also writes per-m-block column partial sums (64 slices).
#define KCH     64
#define NCHUNK  (GG / KCH)        // 64
#define A_HI_O  0
#define A_LO_O  8192
#define B_HI_O  16384
#define B_LO_O  24576
#define STAGE_B 32768             // 32KB
#define GEMM_SMEM (2 * STAGE_B)   // 64KB

__global__ void __launch_bounds__(128, 3)
gemm_fused_kernel(const __nv_bfloat16* __restrict__ Ahi, const __nv_bfloat16* __restrict__ Alo,
                  const __nv_bfloat16* __restrict__ Bhi, const __nv_bfloat16* __restrict__ Blo,
                  const float* __restrict__ beff, float* __restrict__ Z) {
    extern __shared__ __align__(128) char smem[];
    const uint32_t sb = smem_u32(smem);
    const int tid  = threadIdx.x;
    const int wid  = tid >> 5, lane = tid & 31;
    const int wm   = wid & 1;          // 0..1 -> 32-row block
    const int wn   = wid >> 1;         // 0..1 -> 32-col block
    const int m0   = blockIdx.y * 64, n0 = blockIdx.x * 64;

    const __nv_bfloat16* pA0 = Ahi + (size_t)m0 * GG;
    const __nv_bfloat16* pA1 = Alo + (size_t)m0 * GG;
    const __nv_bfloat16* pB0 = Bhi + (size_t)n0 * GG;
    const __nv_bfloat16* pB1 = Blo + (size_t)n0 * GG;

    float acc[2][4][4];
#pragma unroll
    for (int i = 0; i < 2; i++)
#pragma unroll
        for (int j = 0; j < 4; j++)
#pragma unroll
            for (int r = 0; r < 4; r++) acc[i][j][r] = 0.0f;

    const uint32_t aRowO = (uint32_t)(wm * 32 + (lane & 15)) * 128;
    const uint32_t aXor  = lane & 7;
    const uint32_t aHalf = (uint32_t)(lane >> 4);
    const uint32_t bRowO = (uint32_t)(wn * 32 + (lane & 7) + ((lane >> 4) << 3)) * 128;
    const uint32_t bXor  = lane & 7;
    const uint32_t bHalf = (uint32_t)((lane >> 3) & 1);

    auto load_chunk = [&](int u, int s) {
        const uint32_t stb = sb + (uint32_t)s * STAGE_B;
        const size_t kof = (size_t)u * KCH;
#pragma unroll
        for (int j = 0; j < 4; ++j) {
            const int idx = tid + j * 128;
            const int row = idx >> 3, ch = idx & 7;
            const uint32_t so = (uint32_t)row * 128 + (uint32_t)((ch ^ (row & 7)) << 4);
            const size_t go = (size_t)row * GG + kof + (size_t)ch * 8;
            CPA16(stb + A_HI_O + so, pA0 + go);
            CPA16(stb + A_LO_O + so, pA1 + go);
            CPA16(stb + B_HI_O + so, pB0 + go);
            CPA16(stb + B_LO_O + so, pB1 + go);
        }
        CPA_COMMIT();
    };

    load_chunk(0, 0);

    for (int t = 0; t < NCHUNK; ++t) {
        if (t + 1 < NCHUNK) {
            load_chunk(t + 1, (t + 1) & 1);
            asm volatile("cp.async.wait_group 1;" ::: "memory");
        } else {
            asm volatile("cp.async.wait_group 0;" ::: "memory");
        }
        __syncthreads();

        const uint32_t stb = sb + (uint32_t)(t & 1) * STAGE_B;
        const uint32_t aHiB = stb + A_HI_O + aRowO;
        const uint32_t aLoB = stb + A_LO_O + aRowO;
        const uint32_t bHiB = stb + B_HI_O + bRowO;
        const uint32_t bLoB = stb + B_LO_O + bRowO;

#pragma unroll
        for (int ks = 0; ks < 4; ++ks) {
            uint32_t ah[2][4], al[2][4], bh[2][4], bl[2][4];
            const uint32_t asw = (((2u * ks + aHalf) ^ aXor) << 4);
            const uint32_t bsw = (((2u * ks + bHalf) ^ bXor) << 4);
#pragma unroll
            for (int mi = 0; mi < 2; ++mi) {
                LDSM4(ah[mi], aHiB + (uint32_t)mi * 2048 + asw);
                LDSM4(al[mi], aLoB + (uint32_t)mi * 2048 + asw);
            }
#pragma unroll
            for (int p = 0; p < 2; ++p) {
                LDSM4(bh[p], bHiB + (uint32_t)p * 2048 + bsw);
                LDSM4(bl[p], bLoB + (uint32_t)p * 2048 + bsw);
            }
#pragma unroll
            for (int mi = 0; mi < 2; ++mi)
#pragma unroll
                for (int p = 0; p < 2; ++p)
#pragma unroll
                    for (int q = 0; q < 2; ++q) {
                        const int ni = p * 2 + q;
                        mma_bf16(acc[mi][ni], ah[mi], &bh[p][q * 2]);
                        mma_bf16(acc[mi][ni], ah[mi], &bl[p][q * 2]);
                        mma_bf16(acc[mi][ni], al[mi], &bh[p][q * 2]);
                    }
        }
        __syncthreads();
    }

    // epilogue: tanh(acc + beff) -> Z, plus per-CTA column partial sums
    const int rbase = m0 + wm * 32 + (lane >> 2);
    const int cbase = n0 + wn * 32 + (lane & 3) * 2;
    float cs[4][2], cq[4][2];
#pragma unroll
    for (int ni = 0; ni < 4; ++ni) { cs[ni][0] = cs[ni][1] = cq[ni][0] = cq[ni][1] = 0.0f; }

#pragma unroll
    for (int mi = 0; mi < 2; ++mi) {
#pragma unroll
        for (int ni = 0; ni < 4; ++ni) {
            const int col = cbase + ni * 8;
            const float b0 = __ldg(&beff[col]), b1 = __ldg(&beff[col + 1]);
            const int r0 = rbase + mi * 16;
            float t00 = tanhf(acc[mi][ni][0] + b0);
            float t01 = tanhf(acc[mi][ni][1] + b1);
            float t10 = tanhf(acc[mi][ni][2] + b0);
            float t11 = tanhf(acc[mi][ni][3] + b1);
            *(float2*)&Z[(size_t)r0 * NF2 + col]       = make_float2(t00, t01);
            *(float2*)&Z[(size_t)(r0 + 8) * NF2 + col] = make_float2(t10, t11);
            cs[ni][0] += t00 + t10; cq[ni][0] += t00 * t00 + t10 * t10;
            cs[ni][1] += t01 + t11; cq[ni][1] += t01 * t01 + t11 * t11;
        }
    }
    // reduce over lane>>2 groups (stride-4 lanes share a column set)
#pragma unroll
    for (int off = 4; off <= 16; off <<= 1) {
#pragma unroll
        for (int ni = 0; ni < 4; ++ni) {
#pragma unroll
            for (int p = 0; p < 2; ++p) {
                cs[ni][p] += __shfl_down_sync(0xffffffffu, cs[ni][p], off);
                cq[ni][p] += __shfl_down_sync(0xffffffffu, cq[ni][p], off);
            }
        }
    }
    float* sred = (float*)smem;   // reuse pipeline smem (all loads complete)
    if (lane < 4) {
#pragma unroll
        for (int ni = 0; ni < 4; ++ni) {
#pragma unroll
            for (int p = 0; p < 2; ++p) {
                const int cl = wn * 32 + lane * 2 + ni * 8 + p;
                sred[wm * 128 + cl]      = cs[ni][p];
                sred[wm * 128 + 64 + cl] = cq[ni][p];
            }
        }
    }
    __syncthreads();
    if (tid < 64) {
        g_psum[blockIdx.y * 512 + n0 + tid] = sred[tid]      + sred[128 + tid];
        g_psq [blockIdx.y * 512 + n0 + tid] = sred[64 + tid] + sred[192 + tid];
    }
}

// ======================= term layer (+ partial stats) ======================
__global__ void __launch_bounds__(256)
term_kernel(const float* __restrict__ in, int inStride,
            const float* __restrict__ termW, const float* __restrict__ termb,
            int off, int n, float* __restrict__ z) {
    const int t = blockIdx.y;
    const int wid = threadIdx.x >> 5, lane = threadIdx.x & 31;
    __shared__ float Ws[144];
    __shared__ float bs[6];
    __shared__ float rs[8][6], rq[8][6];
    if (threadIdx.x < 144) Ws[threadIdx.x] = termW[(size_t)(off + t) * 144 + threadIdx.x];
    if (threadIdx.x < 6)   bs[threadIdx.x] = termb[(size_t)(off + t) * 6 + threadIdx.x];
    __syncthreads();
    const int b = blockIdx.x * blockDim.x + threadIdx.x;
    float xin[24];
    const float* ip = in + (size_t)b * inStride + t * 24;
#pragma unroll
    for (int i = 0; i < 24; i += 4) *(float4*)&xin[i] = *(const float4*)&ip[i];
    const int C = n * 6;
    float s6[6], q6[6];
#pragma unroll
    for (int h = 0; h < 6; h++) {
        float s = bs[h];
#pragma unroll
        for (int i = 0; i < 24; i++) s = fmaf(xin[i], Ws[h * 24 + i], s);
        float tv = tanhf(s);
        z[(size_t)b * C + t * 6 + h] = tv;
        s6[h] = tv; q6[h] = tv * tv;
    }
#pragma unroll
    for (int offx = 16; offx > 0; offx >>= 1) {
#pragma unroll
        for (int h = 0; h < 6; h++) {
            s6[h] += __shfl_down_sync(0xffffffffu, s6[h], offx);
            q6[h] += __shfl_down_sync(0xffffffffu, q6[h], offx);
        }
    }
    if (lane == 0) {
#pragma unroll
        for (int h = 0; h < 6; h++) { rs[wid][h] = s6[h]; rq[wid][h] = q6[h]; }
    }
    __syncthreads();
    if (threadIdx.x < 6) {
        float s = 0.0f, q = 0.0f;
#pragma unroll
        for (int w = 0; w < 8; w++) { s += rs[w][threadIdx.x]; q += rq[w][threadIdx.x]; }
        g_psum[blockIdx.x * 512 + t * 6 + threadIdx.x] = s;
        g_psq [blockIdx.x * 512 + t * 6 + threadIdx.x] = q;
    }
}

// ======================= BN normalize + aux (stats inline) =================
__global__ void __launch_bounds__(256)
bnaux_kernel(float* __restrict__ zh,
             const float* __restrict__ gamma, const float* __restrict__ beta,
             const float* __restrict__ a1W, const float* __restrict__ a1b,
             const float* __restrict__ a2W, const float* __restrict__ a2b,
             int off, int n, int colOff, int nsli, float* __restrict__ out) {
    const int t = blockIdx.y;
    __shared__ float smu[6], svr[6];
    if (threadIdx.x < 6) {
        const int c = t * 6 + threadIdx.x;
        double s = 0.0, q = 0.0;
        for (int i = 0; i < nsli; i++) {
            s += (double)g_psum[i * 512 + c];
            q += (double)g_psq [i * 512 + c];
        }
        float mu = (float)(s / (double)BB);
        smu[threadIdx.x] = mu;
        svr[threadIdx.x] = (float)(q / (double)BB - (double)mu * (double)mu);
    }
    __syncthreads();
    const int b = blockIdx.x * blockDim.x + threadIdx.x;
    const int C = n * 6;
    float a = a1b[off + t];
#pragma unroll
    for (int k = 0; k < 6; k++) {
        const int c = t * 6 + k;
        float v = zh[(size_t)b * C + c];
        float hv = (v - smu[k]) * rsqrtf(svr[k] + EPSB) * gamma[(size_t)(off + t) * 6 + k]
                   + beta[(size_t)(off + t) * 6 + k];
        zh[(size_t)b * C + c] = hv;
        a = fmaf(hv, a1W[(size_t)(off + t) * 6 + k], a);
    }
    float a1 = tanhf(a);
    out[(size_t)b * OUTC + colOff + t] = fmaf(a1, a2W[off + t], a2b[off + t]);
}

// ======================= final head ========================================
__global__ void __launch_bounds__(256)
final1_kernel(const float* __restrict__ fW, const float* __restrict__ fb) {
    const int wid = threadIdx.x >> 5, lane = threadIdx.x & 31;
    __shared__ float rs[8][6], rq[8][6];
    const int b = blockIdx.x * blockDim.x + threadIdx.x;
    float r[6];
#pragma unroll
    for (int i = 0; i < 6; i++) r[i] = g_h3[(size_t)b * 6 + i];
    float s6[6], q6[6];
#pragma unroll
    for (int o = 0; o < 6; o++) {
        float s = fb[o];
#pragma unroll
        for (int i = 0; i < 6; i++) s = fmaf(r[i], fW[o * 6 + i], s);
        float tv = tanhf(s);
        g_f[(size_t)b * 6 + o] = tv;
        s6[o] = tv; q6[o] = tv * tv;
    }
#pragma unroll
    for (int offx = 16; offx > 0; offx >>= 1) {
#pragma unroll
        for (int h = 0; h < 6; h++) {
            s6[h] += __shfl_down_sync(0xffffffffu, s6[h], offx);
            q6[h] += __shfl_down_sync(0xffffffffu, q6[h], offx);
        }
    }
    if (lane == 0) {
#pragma unroll
        for (int h = 0; h < 6; h++) { rs[wid][h] = s6[h]; rq[wid][h] = q6[h]; }
    }
    __syncthreads();
    if (threadIdx.x < 6) {
        float s = 0.0f, q = 0.0f;
#pragma unroll
        for (int w = 0; w < 8; w++) { s += rs[w][threadIdx.x]; q += rq[w][threadIdx.x]; }
        g_psum[blockIdx.x * 512 + threadIdx.x] = s;
        g_psq [blockIdx.x * 512 + threadIdx.x] = q;
    }
}

__global__ void __launch_bounds__(256)
final2_kernel(const float* __restrict__ fg, const float* __restrict__ fbta,
              const float* __restrict__ fauxW, const float* __restrict__ fauxb,
              const float* __restrict__ foutW, const float* __restrict__ foutb,
              float* __restrict__ out) {
    __shared__ float smu[6], svr[6];
    if (threadIdx.x < 6) {
        double s = 0.0, q = 0.0;
        for (int i = 0; i < 16; i++) {
            s += (double)g_psum[i * 512 + threadIdx.x];
            q += (double)g_psq [i * 512 + threadIdx.x];
        }
        float mu = (float)(s / (double)BB);
        smu[threadIdx.x] = mu;
        svr[threadIdx.x] = (float)(q / (double)BB - (double)mu * (double)mu);
    }
    __syncthreads();
    const int b = blockIdx.x * blockDim.x + threadIdx.x;
    float a = fauxb[0];
#pragma unroll
    for (int h = 0; h < 6; h++) {
        float v = (g_f[(size_t)b * 6 + h] - smu[h]) * rsqrtf(svr[h] + EPSB) * fg[h] + fbta[h];
        a = fmaf(v, fauxW[h], a);
    }
    float fa = tanhf(a);
    float p = fmaf(fa, foutW[0], foutb[0]);
    out[(size_t)b * OUTC + 85] = 1.0f / (1.0f + expf(-p));
}

// ---------------------------------------------------------------------------
extern "C" void kernel_launch(void* const* d_in, const int* in_sizes, int n_in,
                              void* d_out, int out_size) {
    (void)in_sizes; (void)n_in; (void)out_size;
    const float* x      = (const float*)d_in[0];
    const float* geneW  = (const float*)d_in[1];
    const float* geneb  = (const float*)d_in[2];
    const float* termW  = (const float*)d_in[3];
    const float* termb  = (const float*)d_in[4];
    const float* bng    = (const float*)d_in[5];
    const float* bnb    = (const float*)d_in[6];
    const float* a1W    = (const float*)d_in[7];
    const float* a1b    = (const float*)d_in[8];
    const float* a2W    = (const float*)d_in[9];
    const float* a2b    = (const float*)d_in[10];
    const float* finalW = (const float*)d_in[11];
    const float* finalb = (const float*)d_in[12];
    const float* fbng   = (const float*)d_in[13];
    const float* fbnb   = (const float*)d_in[14];
    const float* fauxW  = (const float*)d_in[15];
    const float* fauxb  = (const float*)d_in[16];
    const float* foutW  = (const float*)d_in[17];
    const float* foutb  = (const float*)d_in[18];
    float* out = (float*)d_out;

    float *h0, *h1, *h2, *h3, *beff;
    __nv_bfloat16 *xhi, *xlo, *whi, *wlo;
    cudaGetSymbolAddress((void**)&h0, g_h0);
    cudaGetSymbolAddress((void**)&h1, g_h1);
    cudaGetSymbolAddress((void**)&h2, g_h2);
    cudaGetSymbolAddress((void**)&h3, g_h3);
    cudaGetSymbolAddress((void**)&xhi, g_xhi);
    cudaGetSymbolAddress((void**)&xlo, g_xlo);
    cudaGetSymbolAddress((void**)&whi, g_weffhi);
    cudaGetSymbolAddress((void**)&wlo, g_wefflo);
    cudaGetSymbolAddress((void**)&beff, g_beff);

    // 0) x split + W_eff precompute
    split_kernel<<<(BB * GG / 4 + 255) / 256, 256>>>(x, xhi, xlo, BB * GG / 4);
    {
        dim3 g(GG / 256, 64);
        weff_kernel<<<g, 256>>>(geneW, geneb, termW, termb, whi, wlo, beff);
    }

    // 1) fused gene+term0 GEMM -> tanh z level0 + partial BN stats (64 slices)
    {
        cudaFuncSetAttribute(gemm_fused_kernel,
                             cudaFuncAttributeMaxDynamicSharedMemorySize, GEMM_SMEM);
        dim3 grid(NF2 / 64, BB / 64);
        gemm_fused_kernel<<<grid, 128, GEMM_SMEM>>>(xhi, xlo, whi, wlo, beff, h0);
    }

    // 2) level0 BN + aux (stats inline from 64 slices)
    {
        dim3 gterm(BB / 256, 64);
        bnaux_kernel<<<gterm, 256>>>(h0, bng, bnb, a1W, a1b, a2W, a2b, 0, 64, 0, 64, out);
    }

    // 3) levels 1-3: term (+16-slice partials) then bnaux (stats inline)
    const int   lvl_n[3]        = {16, 4, 1};
    const int   lvl_off[3]      = {64, 80, 84};
    const int   lvl_inStride[3] = {384, 96, 24};
    const float* lvl_in[3]      = {h0, h1, h2};
    float*      lvl_z[3]        = {h1, h2, h3};

    for (int l = 0; l < 3; l++) {
        const int n = lvl_n[l], off = lvl_off[l];
        dim3 gterm(BB / 256, n);
        term_kernel<<<gterm, 256>>>(lvl_in[l], lvl_inStride[l], termW, termb, off, n, lvl_z[l]);
        bnaux_kernel<<<gterm, 256>>>(lvl_z[l], bng, bnb, a1W, a1b, a2W, a2b,
                                     off, n, off, 16, out);
    }

    // 4) final head
    final1_kernel<<<BB / 256, 256>>>(finalW, finalb);
    final2_kernel<<<BB / 256, 256>>>(fbng, fbnb, fauxW, fauxb, foutW, foutb, out);
}

// round 11
// speedup vs baseline: 1.0413x; 1.0413x over previous
#include <cuda_runtime.h>
#include <cuda_bf16.h>
#include <math.h>
#include <stdint.h>

// Problem constants
#define BB   4096
#define GG   4096
#define NF2  384               // fused gene+term0 output width (64 terms x 6)
#define OUTC 86
#define EPSB 1e-5f
#define PSLI 64                // max partial-stat slices

// ---------------- scratch (device globals) ---------------------------------
__device__ __align__(16) float g_h0[BB * 384];
__device__ __align__(16) float g_h1[BB * 96];
__device__ __align__(16) float g_h2[BB * 24];
__device__ __align__(16) float g_h3[BB * 6];
__device__ __align__(16) float g_f [BB * 6];
__device__ float g_mean[512];
__device__ float g_var [512];
__device__ float g_psum[PSLI * 512];
__device__ float g_psq [PSLI * 512];
__device__ __align__(16) __nv_bfloat16 g_xhi[BB * GG];
__device__ __align__(16) __nv_bfloat16 g_xlo[BB * GG];
__device__ __align__(16) __nv_bfloat16 g_weffhi[NF2 * GG];
__device__ __align__(16) __nv_bfloat16 g_wefflo[NF2 * GG];
__device__ float g_beff[NF2];

// ======================= helpers ===========================================
__device__ __forceinline__ uint32_t smem_u32(const void* p) {
    uint32_t a;
    asm("{ .reg .u64 t; cvta.to.shared.u64 t, %1; cvt.u32.u64 %0, t; }" : "=r"(a) : "l"(p));
    return a;
}
#define CPA16(dst, src) \
    asm volatile("cp.async.cg.shared.global [%0], [%1], 16;" :: "r"(dst), "l"(src))
#define CPA_COMMIT() asm volatile("cp.async.commit_group;" ::: "memory")

#define LDSM4(r, addr) \
    asm volatile("ldmatrix.sync.aligned.m8n8.x4.shared.b16 {%0,%1,%2,%3}, [%4];" \
                 : "=r"((r)[0]), "=r"((r)[1]), "=r"((r)[2]), "=r"((r)[3]) : "r"(addr))

__device__ __forceinline__ void mma_bf16(float* d, const uint32_t* a, const uint32_t* b) {
    asm volatile(
        "mma.sync.aligned.m16n8k16.row.col.f32.bf16.bf16.f32 "
        "{%0,%1,%2,%3}, {%4,%5,%6,%7}, {%8,%9}, {%0,%1,%2,%3};"
        : "+f"(d[0]), "+f"(d[1]), "+f"(d[2]), "+f"(d[3])
        : "r"(a[0]), "r"(a[1]), "r"(a[2]), "r"(a[3]), "r"(b[0]), "r"(b[1]));
}

// ======================= fp32 -> bf16 hi/lo split ==========================
__global__ void __launch_bounds__(256)
split_kernel(const float* __restrict__ src, __nv_bfloat16* __restrict__ hi,
             __nv_bfloat16* __restrict__ lo, int n4) {
    int i = blockIdx.x * blockDim.x + threadIdx.x;
    if (i >= n4) return;
    float4 v = ((const float4*)src)[i];
    __nv_bfloat16 h0 = __float2bfloat16(v.x), h1 = __float2bfloat16(v.y);
    __nv_bfloat16 h2 = __float2bfloat16(v.z), h3 = __float2bfloat16(v.w);
    __nv_bfloat16 l0 = __float2bfloat16(v.x - __bfloat162float(h0));
    __nv_bfloat16 l1 = __float2bfloat16(v.y - __bfloat162float(h1));
    __nv_bfloat16 l2 = __float2bfloat16(v.z - __bfloat162float(h2));
    __nv_bfloat16 l3 = __float2bfloat16(v.w - __bfloat162float(h3));
    ((__nv_bfloat162*)hi)[i * 2 + 0] = __nv_bfloat162{h0, h1};
    ((__nv_bfloat162*)hi)[i * 2 + 1] = __nv_bfloat162{h2, h3};
    ((__nv_bfloat162*)lo)[i * 2 + 0] = __nv_bfloat162{l0, l1};
    ((__nv_bfloat162*)lo)[i * 2 + 1] = __nv_bfloat162{l2, l3};
}

// ======================= W_eff precompute ==================================
__global__ void __launch_bounds__(256)
weff_kernel(const float* __restrict__ geneW, const float* __restrict__ geneb,
            const float* __restrict__ termW, const float* __restrict__ termb,
            __nv_bfloat16* __restrict__ whi, __nv_bfloat16* __restrict__ wlo,
            float* __restrict__ beff) {
    const int t = blockIdx.y;
    __shared__ float tw[144];
    if (threadIdx.x < 144) tw[threadIdx.x] = termW[(size_t)t * 144 + threadIdx.x];
    __syncthreads();
    const int g = blockIdx.x * 256 + threadIdx.x;
    float gw[24];
#pragma unroll
    for (int k = 0; k < 24; k++) gw[k] = geneW[((size_t)t * 24 + k) * GG + g];
#pragma unroll
    for (int h = 0; h < 6; h++) {
        float s = 0.0f;
#pragma unroll
        for (int k = 0; k < 24; k++) s = fmaf(tw[h * 24 + k], gw[k], s);
        __nv_bfloat16 hi = __float2bfloat16(s);
        float lo = s - __bfloat162float(hi);
        whi[((size_t)(t * 6 + h)) * GG + g] = hi;
        wlo[((size_t)(t * 6 + h)) * GG + g] = __float2bfloat16(lo);
    }
    if (blockIdx.x == 0 && threadIdx.x < 6) {
        const int h = threadIdx.x;
        float s = termb[t * 6 + h];
#pragma unroll
        for (int k = 0; k < 24; k++) s = fmaf(tw[h * 24 + k], geneb[t * 24 + k], s);
        beff[t * 6 + h] = s;
    }
}

// ======================= fused bf16 GEMM + tanh + partial BN stats =========
#define KCH     64
#define NCHUNK  (GG / KCH)        // 64
#define A_HI_O  0
#define A_LO_O  8192
#define B_HI_O  16384
#define B_LO_O  24576
#define STAGE_B 32768             // 32KB
#define GEMM_SMEM (2 * STAGE_B)   // 64KB

__global__ void __launch_bounds__(128, 3)
gemm_fused_kernel(const __nv_bfloat16* __restrict__ Ahi, const __nv_bfloat16* __restrict__ Alo,
                  const __nv_bfloat16* __restrict__ Bhi, const __nv_bfloat16* __restrict__ Blo,
                  const float* __restrict__ beff, float* __restrict__ Z) {
    extern __shared__ __align__(128) char smem[];
    const uint32_t sb = smem_u32(smem);
    const int tid  = threadIdx.x;
    const int wid  = tid >> 5, lane = tid & 31;
    const int wm   = wid & 1;
    const int wn   = wid >> 1;
    const int m0   = blockIdx.y * 64, n0 = blockIdx.x * 64;

    const __nv_bfloat16* pA0 = Ahi + (size_t)m0 * GG;
    const __nv_bfloat16* pA1 = Alo + (size_t)m0 * GG;
    const __nv_bfloat16* pB0 = Bhi + (size_t)n0 * GG;
    const __nv_bfloat16* pB1 = Blo + (size_t)n0 * GG;

    float acc[2][4][4];
#pragma unroll
    for (int i = 0; i < 2; i++)
#pragma unroll
        for (int j = 0; j < 4; j++)
#pragma unroll
            for (int r = 0; r < 4; r++) acc[i][j][r] = 0.0f;

    const uint32_t aRowO = (uint32_t)(wm * 32 + (lane & 15)) * 128;
    const uint32_t aXor  = lane & 7;
    const uint32_t aHalf = (uint32_t)(lane >> 4);
    const uint32_t bRowO = (uint32_t)(wn * 32 + (lane & 7) + ((lane >> 4) << 3)) * 128;
    const uint32_t bXor  = lane & 7;
    const uint32_t bHalf = (uint32_t)((lane >> 3) & 1);

    auto load_chunk = [&](int u, int s) {
        const uint32_t stb = sb + (uint32_t)s * STAGE_B;
        const size_t kof = (size_t)u * KCH;
#pragma unroll
        for (int j = 0; j < 4; ++j) {
            const int idx = tid + j * 128;
            const int row = idx >> 3, ch = idx & 7;
            const uint32_t so = (uint32_t)row * 128 + (uint32_t)((ch ^ (row & 7)) << 4);
            const size_t go = (size_t)row * GG + kof + (size_t)ch * 8;
            CPA16(stb + A_HI_O + so, pA0 + go);
            CPA16(stb + A_LO_O + so, pA1 + go);
            CPA16(stb + B_HI_O + so, pB0 + go);
            CPA16(stb + B_LO_O + so, pB1 + go);
        }
        CPA_COMMIT();
    };

    load_chunk(0, 0);

    for (int t = 0; t < NCHUNK; ++t) {
        if (t + 1 < NCHUNK) {
            load_chunk(t + 1, (t + 1) & 1);
            asm volatile("cp.async.wait_group 1;" ::: "memory");
        } else {
            asm volatile("cp.async.wait_group 0;" ::: "memory");
        }
        __syncthreads();

        const uint32_t stb = sb + (uint32_t)(t & 1) * STAGE_B;
        const uint32_t aHiB = stb + A_HI_O + aRowO;
        const uint32_t aLoB = stb + A_LO_O + aRowO;
        const uint32_t bHiB = stb + B_HI_O + bRowO;
        const uint32_t bLoB = stb + B_LO_O + bRowO;

#pragma unroll
        for (int ks = 0; ks < 4; ++ks) {
            uint32_t ah[2][4], al[2][4], bh[2][4], bl[2][4];
            const uint32_t asw = (((2u * ks + aHalf) ^ aXor) << 4);
            const uint32_t bsw = (((2u * ks + bHalf) ^ bXor) << 4);
#pragma unroll
            for (int mi = 0; mi < 2; ++mi) {
                LDSM4(ah[mi], aHiB + (uint32_t)mi * 2048 + asw);
                LDSM4(al[mi], aLoB + (uint32_t)mi * 2048 + asw);
            }
#pragma unroll
            for (int p = 0; p < 2; ++p) {
                LDSM4(bh[p], bHiB + (uint32_t)p * 2048 + bsw);
                LDSM4(bl[p], bLoB + (uint32_t)p * 2048 + bsw);
            }
#pragma unroll
            for (int mi = 0; mi < 2; ++mi)
#pragma unroll
                for (int p = 0; p < 2; ++p)
#pragma unroll
                    for (int q = 0; q < 2; ++q) {
                        const int ni = p * 2 + q;
                        mma_bf16(acc[mi][ni], ah[mi], &bh[p][q * 2]);
                        mma_bf16(acc[mi][ni], ah[mi], &bl[p][q * 2]);
                        mma_bf16(acc[mi][ni], al[mi], &bh[p][q * 2]);
                    }
        }
        __syncthreads();
    }

    // epilogue: tanh(acc + beff) -> Z, plus per-CTA column partial sums
    const int rbase = m0 + wm * 32 + (lane >> 2);
    const int cbase = n0 + wn * 32 + (lane & 3) * 2;
    float cs[4][2], cq[4][2];
#pragma unroll
    for (int ni = 0; ni < 4; ++ni) { cs[ni][0] = cs[ni][1] = cq[ni][0] = cq[ni][1] = 0.0f; }

#pragma unroll
    for (int mi = 0; mi < 2; ++mi) {
#pragma unroll
        for (int ni = 0; ni < 4; ++ni) {
            const int col = cbase + ni * 8;
            const float b0 = __ldg(&beff[col]), b1 = __ldg(&beff[col + 1]);
            const int r0 = rbase + mi * 16;
            float t00 = tanhf(acc[mi][ni][0] + b0);
            float t01 = tanhf(acc[mi][ni][1] + b1);
            float t10 = tanhf(acc[mi][ni][2] + b0);
            float t11 = tanhf(acc[mi][ni][3] + b1);
            *(float2*)&Z[(size_t)r0 * NF2 + col]       = make_float2(t00, t01);
            *(float2*)&Z[(size_t)(r0 + 8) * NF2 + col] = make_float2(t10, t11);
            cs[ni][0] += t00 + t10; cq[ni][0] += t00 * t00 + t10 * t10;
            cs[ni][1] += t01 + t11; cq[ni][1] += t01 * t01 + t11 * t11;
        }
    }
#pragma unroll
    for (int off = 4; off <= 16; off <<= 1) {
#pragma unroll
        for (int ni = 0; ni < 4; ++ni) {
#pragma unroll
            for (int p = 0; p < 2; ++p) {
                cs[ni][p] += __shfl_down_sync(0xffffffffu, cs[ni][p], off);
                cq[ni][p] += __shfl_down_sync(0xffffffffu, cq[ni][p], off);
            }
        }
    }
    float* sred = (float*)smem;   // reuse pipeline smem (loads complete)
    if (lane < 4) {
#pragma unroll
        for (int ni = 0; ni < 4; ++ni) {
#pragma unroll
            for (int p = 0; p < 2; ++p) {
                const int cl = wn * 32 + lane * 2 + ni * 8 + p;
                sred[wm * 128 + cl]      = cs[ni][p];
                sred[wm * 128 + 64 + cl] = cq[ni][p];
            }
        }
    }
    __syncthreads();
    if (tid < 64) {
        g_psum[blockIdx.y * 512 + n0 + tid] = sred[tid]      + sred[128 + tid];
        g_psq [blockIdx.y * 512 + n0 + tid] = sred[64 + tid] + sred[192 + tid];
    }
}

// ======================= stats finalize (one tiny launch) ==================
__global__ void __launch_bounds__(512)
stats2_kernel(int C, int nsli) {
    const int c = threadIdx.x;
    if (c >= C) return;
    double s = 0.0, q = 0.0;
    for (int i = 0; i < nsli; ++i) {
        s += (double)g_psum[i * 512 + c];
        q += (double)g_psq [i * 512 + c];
    }
    float mu = (float)(s / (double)BB);
    g_mean[c] = mu;
    g_var[c]  = (float)(q / (double)BB - (double)mu * (double)mu);
}

// ======================= term layer (+ partial stats) ======================
__global__ void __launch_bounds__(256)
term_kernel(const float* __restrict__ in, int inStride,
            const float* __restrict__ termW, const float* __restrict__ termb,
            int off, int n, float* __restrict__ z) {
    const int t = blockIdx.y;
    const int wid = threadIdx.x >> 5, lane = threadIdx.x & 31;
    __shared__ float Ws[144];
    __shared__ float bs[6];
    __shared__ float rs[8][6], rq[8][6];
    if (threadIdx.x < 144) Ws[threadIdx.x] = termW[(size_t)(off + t) * 144 + threadIdx.x];
    if (threadIdx.x < 6)   bs[threadIdx.x] = termb[(size_t)(off + t) * 6 + threadIdx.x];
    __syncthreads();
    const int b = blockIdx.x * blockDim.x + threadIdx.x;
    float xin[24];
    const float* ip = in + (size_t)b * inStride + t * 24;
#pragma unroll
    for (int i = 0; i < 24; i += 4) *(float4*)&xin[i] = *(const float4*)&ip[i];
    const int C = n * 6;
    float s6[6], q6[6];
#pragma unroll
    for (int h = 0; h < 6; h++) {
        float s = bs[h];
#pragma unroll
        for (int i = 0; i < 24; i++) s = fmaf(xin[i], Ws[h * 24 + i], s);
        float tv = tanhf(s);
        z[(size_t)b * C + t * 6 + h] = tv;
        s6[h] = tv; q6[h] = tv * tv;
    }
#pragma unroll
    for (int offx = 16; offx > 0; offx >>= 1) {
#pragma unroll
        for (int h = 0; h < 6; h++) {
            s6[h] += __shfl_down_sync(0xffffffffu, s6[h], offx);
            q6[h] += __shfl_down_sync(0xffffffffu, q6[h], offx);
        }
    }
    if (lane == 0) {
#pragma unroll
        for (int h = 0; h < 6; h++) { rs[wid][h] = s6[h]; rq[wid][h] = q6[h]; }
    }
    __syncthreads();
    if (threadIdx.x < 6) {
        float s = 0.0f, q = 0.0f;
#pragma unroll
        for (int w = 0; w < 8; w++) { s += rs[w][threadIdx.x]; q += rq[w][threadIdx.x]; }
        g_psum[blockIdx.x * 512 + t * 6 + threadIdx.x] = s;
        g_psq [blockIdx.x * 512 + t * 6 + threadIdx.x] = q;
    }
}

// ======================= BN normalize + aux (reads g_mean/g_var) ===========
__global__ void __launch_bounds__(256)
bnaux_kernel(float* __restrict__ zh,
             const float* __restrict__ gamma, const float* __restrict__ beta,
             const float* __restrict__ a1W, const float* __restrict__ a1b,
             const float* __restrict__ a2W, const float* __restrict__ a2b,
             int off, int n, int colOff, float* __restrict__ out) {
    const int t = blockIdx.y;
    const int b = blockIdx.x * blockDim.x + threadIdx.x;
    const int C = n * 6;
    float a = a1b[off + t];
#pragma unroll
    for (int k = 0; k < 6; k++) {
        const int c = t * 6 + k;
        float v = zh[(size_t)b * C + c];
        float hv = (v - g_mean[c]) * rsqrtf(g_var[c] + EPSB) * gamma[(size_t)(off + t) * 6 + k]
                   + beta[(size_t)(off + t) * 6 + k];
        zh[(size_t)b * C + c] = hv;
        a = fmaf(hv, a1W[(size_t)(off + t) * 6 + k], a);
    }
    float a1 = tanhf(a);
    out[(size_t)b * OUTC + colOff + t] = fmaf(a1, a2W[off + t], a2b[off + t]);
}

// ======================= final head ========================================
__global__ void __launch_bounds__(256)
final1_kernel(const float* __restrict__ fW, const float* __restrict__ fb) {
    const int wid = threadIdx.x >> 5, lane = threadIdx.x & 31;
    __shared__ float rs[8][6], rq[8][6];
    const int b = blockIdx.x * blockDim.x + threadIdx.x;
    float r[6];
#pragma unroll
    for (int i = 0; i < 6; i++) r[i] = g_h3[(size_t)b * 6 + i];
    float s6[6], q6[6];
#pragma unroll
    for (int o = 0; o < 6; o++) {
        float s = fb[o];
#pragma unroll
        for (int i = 0; i < 6; i++) s = fmaf(r[i], fW[o * 6 + i], s);
        float tv = tanhf(s);
        g_f[(size_t)b * 6 + o] = tv;
        s6[o] = tv; q6[o] = tv * tv;
    }
#pragma unroll
    for (int offx = 16; offx > 0; offx >>= 1) {
#pragma unroll
        for (int h = 0; h < 6; h++) {
            s6[h] += __shfl_down_sync(0xffffffffu, s6[h], offx);
            q6[h] += __shfl_down_sync(0xffffffffu, q6[h], offx);
        }
    }
    if (lane == 0) {
#pragma unroll
        for (int h = 0; h < 6; h++) { rs[wid][h] = s6[h]; rq[wid][h] = q6[h]; }
    }
    __syncthreads();
    if (threadIdx.x < 6) {
        float s = 0.0f, q = 0.0f;
#pragma unroll
        for (int w = 0; w < 8; w++) { s += rs[w][threadIdx.x]; q += rq[w][threadIdx.x]; }
        g_psum[blockIdx.x * 512 + threadIdx.x] = s;
        g_psq [blockIdx.x * 512 + threadIdx.x] = q;
    }
}

__global__ void __launch_bounds__(256)
final2_kernel(const float* __restrict__ fg, const float* __restrict__ fbta,
              const float* __restrict__ fauxW, const float* __restrict__ fauxb,
              const float* __restrict__ foutW, const float* __restrict__ foutb,
              float* __restrict__ out) {
    const int b = blockIdx.x * blockDim.x + threadIdx.x;
    float a = fauxb[0];
#pragma unroll
    for (int h = 0; h < 6; h++) {
        float v = (g_f[(size_t)b * 6 + h] - g_mean[h]) * rsqrtf(g_var[h] + EPSB) * fg[h] + fbta[h];
        a = fmaf(v, fauxW[h], a);
    }
    float fa = tanhf(a);
    float p = fmaf(fa, foutW[0], foutb[0]);
    out[(size_t)b * OUTC + 85] = 1.0f / (1.0f + expf(-p));
}

// ---------------------------------------------------------------------------
extern "C" void kernel_launch(void* const* d_in, const int* in_sizes, int n_in,
                              void* d_out, int out_size) {
    (void)in_sizes; (void)n_in; (void)out_size;
    const float* x      = (const float*)d_in[0];
    const float* geneW  = (const float*)d_in[1];
    const float* geneb  = (const float*)d_in[2];
    const float* termW  = (const float*)d_in[3];
    const float* termb  = (const float*)d_in[4];
    const float* bng    = (const float*)d_in[5];
    const float* bnb    = (const float*)d_in[6];
    const float* a1W    = (const float*)d_in[7];
    const float* a1b    = (const float*)d_in[8];
    const float* a2W    = (const float*)d_in[9];
    const float* a2b    = (const float*)d_in[10];
    const float* finalW = (const float*)d_in[11];
    const float* finalb = (const float*)d_in[12];
    const float* fbng   = (const float*)d_in[13];
    const float* fbnb   = (const float*)d_in[14];
    const float* fauxW  = (const float*)d_in[15];
    const float* fauxb  = (const float*)d_in[16];
    const float* foutW  = (const float*)d_in[17];
    const float* foutb  = (const float*)d_in[18];
    float* out = (float*)d_out;

    float *h0, *h1, *h2, *h3, *beff;
    __nv_bfloat16 *xhi, *xlo, *whi, *wlo;
    cudaGetSymbolAddress((void**)&h0, g_h0);
    cudaGetSymbolAddress((void**)&h1, g_h1);
    cudaGetSymbolAddress((void**)&h2, g_h2);
    cudaGetSymbolAddress((void**)&h3, g_h3);
    cudaGetSymbolAddress((void**)&xhi, g_xhi);
    cudaGetSymbolAddress((void**)&xlo, g_xlo);
    cudaGetSymbolAddress((void**)&whi, g_weffhi);
    cudaGetSymbolAddress((void**)&wlo, g_wefflo);
    cudaGetSymbolAddress((void**)&beff, g_beff);

    // 0) x split + W_eff precompute
    split_kernel<<<(BB * GG / 4 + 255) / 256, 256>>>(x, xhi, xlo, BB * GG / 4);
    {
        dim3 g(GG / 256, 64);
        weff_kernel<<<g, 256>>>(geneW, geneb, termW, termb, whi, wlo, beff);
    }

    // 1) fused gene+term0 GEMM -> tanh z level0 + partial BN stats (64 slices)
    {
        cudaFuncSetAttribute(gemm_fused_kernel,
                             cudaFuncAttributeMaxDynamicSharedMemorySize, GEMM_SMEM);
        dim3 grid(NF2 / 64, BB / 64);
        gemm_fused_kernel<<<grid, 128, GEMM_SMEM>>>(xhi, xlo, whi, wlo, beff, h0);
    }

    // 2) level0: finalize stats once, then BN + aux
    stats2_kernel<<<1, 512>>>(384, 64);
    {
        dim3 gterm(BB / 256, 64);
        bnaux_kernel<<<gterm, 256>>>(h0, bng, bnb, a1W, a1b, a2W, a2b, 0, 64, 0, out);
    }

    // 3) levels 1-3: term (+16-slice partials), finalize, bnaux
    const int   lvl_n[3]        = {16, 4, 1};
    const int   lvl_off[3]      = {64, 80, 84};
    const int   lvl_inStride[3] = {384, 96, 24};
    const float* lvl_in[3]      = {h0, h1, h2};
    float*      lvl_z[3]        = {h1, h2, h3};

    for (int l = 0; l < 3; l++) {
        const int n = lvl_n[l], off = lvl_off[l];
        dim3 gterm(BB / 256, n);
        term_kernel<<<gterm, 256>>>(lvl_in[l], lvl_inStride[l], termW, termb, off, n, lvl_z[l]);
        stats2_kernel<<<1, 512>>>(n * 6, 16);
        bnaux_kernel<<<gterm, 256>>>(lvl_z[l], bng, bnb, a1W, a1b, a2W, a2b,
                                     off, n, off, out);
    }

    // 4) final head
    final1_kernel<<<BB / 256, 256>>>(finalW, finalb);
    stats2_kernel<<<1, 512>>>(6, 16);
    final2_kernel<<<BB / 256, 256>>>(fbng, fbnb, fauxW, fauxb, foutW, foutb, out);
}

// round 12
// speedup vs baseline: 1.7608x; 1.6910x over previous
#include <cuda_runtime.h>
#include <cuda_bf16.h>
#include <math.h>
#include <stdint.h>

// Problem constants
#define BB   4096
#define GG   4096
#define NF2  384               // fused gene+term0 output width (64 terms x 6)
#define OUTC 86
#define EPSB 1e-5f
#define PSLI 64                // max partial-stat slices

// ---------------- scratch (device globals) ---------------------------------
__device__ __align__(16) float g_h0[BB * 384];
__device__ __align__(16) float g_h1[BB * 96];
__device__ __align__(16) float g_h2[BB * 24];
__device__ __align__(16) float g_h3[BB * 6];
__device__ __align__(16) float g_f [BB * 6];
__device__ float g_mean[512];
__device__ float g_var [512];
__device__ float g_psum[PSLI * 512];
__device__ float g_psq [PSLI * 512];
__device__ __align__(16) __nv_bfloat16 g_xhi[BB * GG];
__device__ __align__(16) __nv_bfloat16 g_xlo[BB * GG];
__device__ __align__(16) __nv_bfloat16 g_weffhi[NF2 * GG];
__device__ __align__(16) __nv_bfloat16 g_wefflo[NF2 * GG];
__device__ float g_beff[NF2];

// ======================= helpers ===========================================
__device__ __forceinline__ uint32_t smem_u32(const void* p) {
    uint32_t a;
    asm("{ .reg .u64 t; cvta.to.shared.u64 t, %1; cvt.u32.u64 %0, t; }" : "=r"(a) : "l"(p));
    return a;
}
#define CPA16(dst, src) \
    asm volatile("cp.async.cg.shared.global [%0], [%1], 16;" :: "r"(dst), "l"(src))
#define CPA_COMMIT() asm volatile("cp.async.commit_group;" ::: "memory")

#define LDSM4(r, addr) \
    asm volatile("ldmatrix.sync.aligned.m8n8.x4.shared.b16 {%0,%1,%2,%3}, [%4];" \
                 : "=r"((r)[0]), "=r"((r)[1]), "=r"((r)[2]), "=r"((r)[3]) : "r"(addr))

__device__ __forceinline__ void mma_bf16(float* d, const uint32_t* a, const uint32_t* b) {
    asm volatile(
        "mma.sync.aligned.m16n8k16.row.col.f32.bf16.bf16.f32 "
        "{%0,%1,%2,%3}, {%4,%5,%6,%7}, {%8,%9}, {%0,%1,%2,%3};"
        : "+f"(d[0]), "+f"(d[1]), "+f"(d[2]), "+f"(d[3])
        : "r"(a[0]), "r"(a[1]), "r"(a[2]), "r"(a[3]), "r"(b[0]), "r"(b[1]));
}

// ======================= fp32 -> bf16 hi/lo split ==========================
__global__ void __launch_bounds__(256)
split_kernel(const float* __restrict__ src, __nv_bfloat16* __restrict__ hi,
             __nv_bfloat16* __restrict__ lo, int n4) {
    int i = blockIdx.x * blockDim.x + threadIdx.x;
    if (i >= n4) return;
    float4 v = ((const float4*)src)[i];
    __nv_bfloat16 h0 = __float2bfloat16(v.x), h1 = __float2bfloat16(v.y);
    __nv_bfloat16 h2 = __float2bfloat16(v.z), h3 = __float2bfloat16(v.w);
    __nv_bfloat16 l0 = __float2bfloat16(v.x - __bfloat162float(h0));
    __nv_bfloat16 l1 = __float2bfloat16(v.y - __bfloat162float(h1));
    __nv_bfloat16 l2 = __float2bfloat16(v.z - __bfloat162float(h2));
    __nv_bfloat16 l3 = __float2bfloat16(v.w - __bfloat162float(h3));
    ((__nv_bfloat162*)hi)[i * 2 + 0] = __nv_bfloat162{h0, h1};
    ((__nv_bfloat162*)hi)[i * 2 + 1] = __nv_bfloat162{h2, h3};
    ((__nv_bfloat162*)lo)[i * 2 + 0] = __nv_bfloat162{l0, l1};
    ((__nv_bfloat162*)lo)[i * 2 + 1] = __nv_bfloat162{l2, l3};
}

// ======================= W_eff precompute ==================================
__global__ void __launch_bounds__(256)
weff_kernel(const float* __restrict__ geneW, const float* __restrict__ geneb,
            const float* __restrict__ termW, const float* __restrict__ termb,
            __nv_bfloat16* __restrict__ whi, __nv_bfloat16* __restrict__ wlo,
            float* __restrict__ beff) {
    const int t = blockIdx.y;
    __shared__ float tw[144];
    if (threadIdx.x < 144) tw[threadIdx.x] = termW[(size_t)t * 144 + threadIdx.x];
    __syncthreads();
    const int g = blockIdx.x * 256 + threadIdx.x;
    float gw[24];
#pragma unroll
    for (int k = 0; k < 24; k++) gw[k] = geneW[((size_t)t * 24 + k) * GG + g];
#pragma unroll
    for (int h = 0; h < 6; h++) {
        float s = 0.0f;
#pragma unroll
        for (int k = 0; k < 24; k++) s = fmaf(tw[h * 24 + k], gw[k], s);
        __nv_bfloat16 hi = __float2bfloat16(s);
        float lo = s - __bfloat162float(hi);
        whi[((size_t)(t * 6 + h)) * GG + g] = hi;
        wlo[((size_t)(t * 6 + h)) * GG + g] = __float2bfloat16(lo);
    }
    if (blockIdx.x == 0 && threadIdx.x < 6) {
        const int h = threadIdx.x;
        float s = termb[t * 6 + h];
#pragma unroll
        for (int k = 0; k < 24; k++) s = fmaf(tw[h * 24 + k], geneb[t * 24 + k], s);
        beff[t * 6 + h] = s;
    }
}

// ======================= fused bf16 GEMM + tanh + partial BN stats =========
#define KCH     64
#define NCHUNK  (GG / KCH)        // 64
#define A_HI_O  0
#define A_LO_O  8192
#define B_HI_O  16384
#define B_LO_O  24576
#define STAGE_B 32768             // 32KB
#define GEMM_SMEM (2 * STAGE_B)   // 64KB

__global__ void __launch_bounds__(128, 3)
gemm_fused_kernel(const __nv_bfloat16* __restrict__ Ahi, const __nv_bfloat16* __restrict__ Alo,
                  const __nv_bfloat16* __restrict__ Bhi, const __nv_bfloat16* __restrict__ Blo,
                  const float* __restrict__ beff, float* __restrict__ Z) {
    extern __shared__ __align__(128) char smem[];
    const uint32_t sb = smem_u32(smem);
    const int tid  = threadIdx.x;
    const int wid  = tid >> 5, lane = tid & 31;
    const int wm   = wid & 1;
    const int wn   = wid >> 1;
    const int m0   = blockIdx.y * 64, n0 = blockIdx.x * 64;

    const __nv_bfloat16* pA0 = Ahi + (size_t)m0 * GG;
    const __nv_bfloat16* pA1 = Alo + (size_t)m0 * GG;
    const __nv_bfloat16* pB0 = Bhi + (size_t)n0 * GG;
    const __nv_bfloat16* pB1 = Blo + (size_t)n0 * GG;

    float acc[2][4][4];
#pragma unroll
    for (int i = 0; i < 2; i++)
#pragma unroll
        for (int j = 0; j < 4; j++)
#pragma unroll
            for (int r = 0; r < 4; r++) acc[i][j][r] = 0.0f;

    const uint32_t aRowO = (uint32_t)(wm * 32 + (lane & 15)) * 128;
    const uint32_t aXor  = lane & 7;
    const uint32_t aHalf = (uint32_t)(lane >> 4);
    const uint32_t bRowO = (uint32_t)(wn * 32 + (lane & 7) + ((lane >> 4) << 3)) * 128;
    const uint32_t bXor  = lane & 7;
    const uint32_t bHalf = (uint32_t)((lane >> 3) & 1);

    auto load_chunk = [&](int u, int s) {
        const uint32_t stb = sb + (uint32_t)s * STAGE_B;
        const size_t kof = (size_t)u * KCH;
#pragma unroll
        for (int j = 0; j < 4; ++j) {
            const int idx = tid + j * 128;
            const int row = idx >> 3, ch = idx & 7;
            const uint32_t so = (uint32_t)row * 128 + (uint32_t)((ch ^ (row & 7)) << 4);
            const size_t go = (size_t)row * GG + kof + (size_t)ch * 8;
            CPA16(stb + A_HI_O + so, pA0 + go);
            CPA16(stb + A_LO_O + so, pA1 + go);
            CPA16(stb + B_HI_O + so, pB0 + go);
            CPA16(stb + B_LO_O + so, pB1 + go);
        }
        CPA_COMMIT();
    };

    load_chunk(0, 0);

    for (int t = 0; t < NCHUNK; ++t) {
        if (t + 1 < NCHUNK) {
            load_chunk(t + 1, (t + 1) & 1);
            asm volatile("cp.async.wait_group 1;" ::: "memory");
        } else {
            asm volatile("cp.async.wait_group 0;" ::: "memory");
        }
        __syncthreads();

        const uint32_t stb = sb + (uint32_t)(t & 1) * STAGE_B;
        const uint32_t aHiB = stb + A_HI_O + aRowO;
        const uint32_t aLoB = stb + A_LO_O + aRowO;
        const uint32_t bHiB = stb + B_HI_O + bRowO;
        const uint32_t bLoB = stb + B_LO_O + bRowO;

#pragma unroll
        for (int ks = 0; ks < 4; ++ks) {
            uint32_t ah[2][4], al[2][4], bh[2][4], bl[2][4];
            const uint32_t asw = (((2u * ks + aHalf) ^ aXor) << 4);
            const uint32_t bsw = (((2u * ks + bHalf) ^ bXor) << 4);
#pragma unroll
            for (int mi = 0; mi < 2; ++mi) {
                LDSM4(ah[mi], aHiB + (uint32_t)mi * 2048 + asw);
                LDSM4(al[mi], aLoB + (uint32_t)mi * 2048 + asw);
            }
#pragma unroll
            for (int p = 0; p < 2; ++p) {
                LDSM4(bh[p], bHiB + (uint32_t)p * 2048 + bsw);
                LDSM4(bl[p], bLoB + (uint32_t)p * 2048 + bsw);
            }
#pragma unroll
            for (int mi = 0; mi < 2; ++mi)
#pragma unroll
                for (int p = 0; p < 2; ++p)
#pragma unroll
                    for (int q = 0; q < 2; ++q) {
                        const int ni = p * 2 + q;
                        mma_bf16(acc[mi][ni], ah[mi], &bh[p][q * 2]);
                        mma_bf16(acc[mi][ni], ah[mi], &bl[p][q * 2]);
                        mma_bf16(acc[mi][ni], al[mi], &bh[p][q * 2]);
                    }
        }
        __syncthreads();
    }

    // epilogue: tanh(acc + beff) -> Z, plus per-CTA column partial sums
    const int rbase = m0 + wm * 32 + (lane >> 2);
    const int cbase = n0 + wn * 32 + (lane & 3) * 2;
    float cs[4][2], cq[4][2];
#pragma unroll
    for (int ni = 0; ni < 4; ++ni) { cs[ni][0] = cs[ni][1] = cq[ni][0] = cq[ni][1] = 0.0f; }

#pragma unroll
    for (int mi = 0; mi < 2; ++mi) {
#pragma unroll
        for (int ni = 0; ni < 4; ++ni) {
            const int col = cbase + ni * 8;
            const float b0 = __ldg(&beff[col]), b1 = __ldg(&beff[col + 1]);
            const int r0 = rbase + mi * 16;
            float t00 = tanhf(acc[mi][ni][0] + b0);
            float t01 = tanhf(acc[mi][ni][1] + b1);
            float t10 = tanhf(acc[mi][ni][2] + b0);
            float t11 = tanhf(acc[mi][ni][3] + b1);
            *(float2*)&Z[(size_t)r0 * NF2 + col]       = make_float2(t00, t01);
            *(float2*)&Z[(size_t)(r0 + 8) * NF2 + col] = make_float2(t10, t11);
            cs[ni][0] += t00 + t10; cq[ni][0] += t00 * t00 + t10 * t10;
            cs[ni][1] += t01 + t11; cq[ni][1] += t01 * t01 + t11 * t11;
        }
    }
#pragma unroll
    for (int off = 4; off <= 16; off <<= 1) {
#pragma unroll
        for (int ni = 0; ni < 4; ++ni) {
#pragma unroll
            for (int p = 0; p < 2; ++p) {
                cs[ni][p] += __shfl_down_sync(0xffffffffu, cs[ni][p], off);
                cq[ni][p] += __shfl_down_sync(0xffffffffu, cq[ni][p], off);
            }
        }
    }
    float* sred = (float*)smem;   // reuse pipeline smem (loads complete)
    if (lane < 4) {
#pragma unroll
        for (int ni = 0; ni < 4; ++ni) {
#pragma unroll
            for (int p = 0; p < 2; ++p) {
                const int cl = wn * 32 + lane * 2 + ni * 8 + p;
                sred[wm * 128 + cl]      = cs[ni][p];
                sred[wm * 128 + 64 + cl] = cq[ni][p];
            }
        }
    }
    __syncthreads();
    if (tid < 64) {
        g_psum[blockIdx.y * 512 + n0 + tid] = sred[tid]      + sred[128 + tid];
        g_psq [blockIdx.y * 512 + n0 + tid] = sred[64 + tid] + sred[192 + tid];
    }
}

// ======================= stats finalize (warp-parallel slices) =============
// block = 256 = 8 channels x 32 lanes; lane -> slice(s). fp64 shuffle tree.
__global__ void __launch_bounds__(256)
stats2_kernel(int C, int nsli) {
    const int lane = threadIdx.x & 31;
    const int ch   = threadIdx.x >> 5;
    const int c    = blockIdx.x * 8 + ch;
    if (c >= C) return;
    double s = 0.0, q = 0.0;
    if (lane < nsli) {
        s = (double)g_psum[lane * 512 + c];
        q = (double)g_psq [lane * 512 + c];
    }
    if (lane + 32 < nsli) {
        s += (double)g_psum[(lane + 32) * 512 + c];
        q += (double)g_psq [(lane + 32) * 512 + c];
    }
#pragma unroll
    for (int off = 16; off > 0; off >>= 1) {
        s += __shfl_down_sync(0xffffffffu, s, off);
        q += __shfl_down_sync(0xffffffffu, q, off);
    }
    if (lane == 0) {
        float mu = (float)(s / (double)BB);
        g_mean[c] = mu;
        g_var[c]  = (float)(q / (double)BB - (double)mu * (double)mu);
    }
}

// ======================= term layer (+ partial stats) ======================
__global__ void __launch_bounds__(256)
term_kernel(const float* __restrict__ in, int inStride,
            const float* __restrict__ termW, const float* __restrict__ termb,
            int off, int n, float* __restrict__ z) {
    const int t = blockIdx.y;
    const int wid = threadIdx.x >> 5, lane = threadIdx.x & 31;
    __shared__ float Ws[144];
    __shared__ float bs[6];
    __shared__ float rs[8][6], rq[8][6];
    if (threadIdx.x < 144) Ws[threadIdx.x] = termW[(size_t)(off + t) * 144 + threadIdx.x];
    if (threadIdx.x < 6)   bs[threadIdx.x] = termb[(size_t)(off + t) * 6 + threadIdx.x];
    __syncthreads();
    const int b = blockIdx.x * blockDim.x + threadIdx.x;
    float xin[24];
    const float* ip = in + (size_t)b * inStride + t * 24;
#pragma unroll
    for (int i = 0; i < 24; i += 4) *(float4*)&xin[i] = *(const float4*)&ip[i];
    const int C = n * 6;
    float s6[6], q6[6];
#pragma unroll
    for (int h = 0; h < 6; h++) {
        float s = bs[h];
#pragma unroll
        for (int i = 0; i < 24; i++) s = fmaf(xin[i], Ws[h * 24 + i], s);
        float tv = tanhf(s);
        z[(size_t)b * C + t * 6 + h] = tv;
        s6[h] = tv; q6[h] = tv * tv;
    }
#pragma unroll
    for (int offx = 16; offx > 0; offx >>= 1) {
#pragma unroll
        for (int h = 0; h < 6; h++) {
            s6[h] += __shfl_down_sync(0xffffffffu, s6[h], offx);
            q6[h] += __shfl_down_sync(0xffffffffu, q6[h], offx);
        }
    }
    if (lane == 0) {
#pragma unroll
        for (int h = 0; h < 6; h++) { rs[wid][h] = s6[h]; rq[wid][h] = q6[h]; }
    }
    __syncthreads();
    if (threadIdx.x < 6) {
        float s = 0.0f, q = 0.0f;
#pragma unroll
        for (int w = 0; w < 8; w++) { s += rs[w][threadIdx.x]; q += rq[w][threadIdx.x]; }
        g_psum[blockIdx.x * 512 + t * 6 + threadIdx.x] = s;
        g_psq [blockIdx.x * 512 + t * 6 + threadIdx.x] = q;
    }
}

// ======================= BN normalize + aux (reads g_mean/g_var) ===========
__global__ void __launch_bounds__(256)
bnaux_kernel(float* __restrict__ zh,
             const float* __restrict__ gamma, const float* __restrict__ beta,
             const float* __restrict__ a1W, const float* __restrict__ a1b,
             const float* __restrict__ a2W, const float* __restrict__ a2b,
             int off, int n, int colOff, float* __restrict__ out) {
    const int t = blockIdx.y;
    const int b = blockIdx.x * blockDim.x + threadIdx.x;
    const int C = n * 6;
    float a = a1b[off + t];
#pragma unroll
    for (int k = 0; k < 6; k++) {
        const int c = t * 6 + k;
        float v = zh[(size_t)b * C + c];
        float hv = (v - g_mean[c]) * rsqrtf(g_var[c] + EPSB) * gamma[(size_t)(off + t) * 6 + k]
                   + beta[(size_t)(off + t) * 6 + k];
        zh[(size_t)b * C + c] = hv;
        a = fmaf(hv, a1W[(size_t)(off + t) * 6 + k], a);
    }
    float a1 = tanhf(a);
    out[(size_t)b * OUTC + colOff + t] = fmaf(a1, a2W[off + t], a2b[off + t]);
}

// ======================= final head ========================================
__global__ void __launch_bounds__(256)
final1_kernel(const float* __restrict__ fW, const float* __restrict__ fb) {
    const int wid = threadIdx.x >> 5, lane = threadIdx.x & 31;
    __shared__ float rs[8][6], rq[8][6];
    const int b = blockIdx.x * blockDim.x + threadIdx.x;
    float r[6];
#pragma unroll
    for (int i = 0; i < 6; i++) r[i] = g_h3[(size_t)b * 6 + i];
    float s6[6], q6[6];
#pragma unroll
    for (int o = 0; o < 6; o++) {
        float s = fb[o];
#pragma unroll
        for (int i = 0; i < 6; i++) s = fmaf(r[i], fW[o * 6 + i], s);
        float tv = tanhf(s);
        g_f[(size_t)b * 6 + o] = tv;
        s6[o] = tv; q6[o] = tv * tv;
    }
#pragma unroll
    for (int offx = 16; offx > 0; offx >>= 1) {
#pragma unroll
        for (int h = 0; h < 6; h++) {
            s6[h] += __shfl_down_sync(0xffffffffu, s6[h], offx);
            q6[h] += __shfl_down_sync(0xffffffffu, q6[h], offx);
        }
    }
    if (lane == 0) {
#pragma unroll
        for (int h = 0; h < 6; h++) { rs[wid][h] = s6[h]; rq[wid][h] = q6[h]; }
    }
    __syncthreads();
    if (threadIdx.x < 6) {
        float s = 0.0f, q = 0.0f;
#pragma unroll
        for (int w = 0; w < 8; w++) { s += rs[w][threadIdx.x]; q += rq[w][threadIdx.x]; }
        g_psum[blockIdx.x * 512 + threadIdx.x] = s;
        g_psq [blockIdx.x * 512 + threadIdx.x] = q;
    }
}

__global__ void __launch_bounds__(256)
final2_kernel(const float* __restrict__ fg, const float* __restrict__ fbta,
              const float* __restrict__ fauxW, const float* __restrict__ fauxb,
              const float* __restrict__ foutW, const float* __restrict__ foutb,
              float* __restrict__ out) {
    const int b = blockIdx.x * blockDim.x + threadIdx.x;
    float a = fauxb[0];
#pragma unroll
    for (int h = 0; h < 6; h++) {
        float v = (g_f[(size_t)b * 6 + h] - g_mean[h]) * rsqrtf(g_var[h] + EPSB) * fg[h] + fbta[h];
        a = fmaf(v, fauxW[h], a);
    }
    float fa = tanhf(a);
    float p = fmaf(fa, foutW[0], foutb[0]);
    out[(size_t)b * OUTC + 85] = 1.0f / (1.0f + expf(-p));
}

// ---------------------------------------------------------------------------
extern "C" void kernel_launch(void* const* d_in, const int* in_sizes, int n_in,
                              void* d_out, int out_size) {
    (void)in_sizes; (void)n_in; (void)out_size;
    const float* x      = (const float*)d_in[0];
    const float* geneW  = (const float*)d_in[1];
    const float* geneb  = (const float*)d_in[2];
    const float* termW  = (const float*)d_in[3];
    const float* termb  = (const float*)d_in[4];
    const float* bng    = (const float*)d_in[5];
    const float* bnb    = (const float*)d_in[6];
    const float* a1W    = (const float*)d_in[7];
    const float* a1b    = (const float*)d_in[8];
    const float* a2W    = (const float*)d_in[9];
    const float* a2b    = (const float*)d_in[10];
    const float* finalW = (const float*)d_in[11];
    const float* finalb = (const float*)d_in[12];
    const float* fbng   = (const float*)d_in[13];
    const float* fbnb   = (const float*)d_in[14];
    const float* fauxW  = (const float*)d_in[15];
    const float* fauxb  = (const float*)d_in[16];
    const float* foutW  = (const float*)d_in[17];
    const float* foutb  = (const float*)d_in[18];
    float* out = (float*)d_out;

    float *h0, *h1, *h2, *h3, *beff;
    __nv_bfloat16 *xhi, *xlo, *whi, *wlo;
    cudaGetSymbolAddress((void**)&h0, g_h0);
    cudaGetSymbolAddress((void**)&h1, g_h1);
    cudaGetSymbolAddress((void**)&h2, g_h2);
    cudaGetSymbolAddress((void**)&h3, g_h3);
    cudaGetSymbolAddress((void**)&xhi, g_xhi);
    cudaGetSymbolAddress((void**)&xlo, g_xlo);
    cudaGetSymbolAddress((void**)&whi, g_weffhi);
    cudaGetSymbolAddress((void**)&wlo, g_wefflo);
    cudaGetSymbolAddress((void**)&beff, g_beff);

    // 0) x split + W_eff precompute
    split_kernel<<<(BB * GG / 4 + 255) / 256, 256>>>(x, xhi, xlo, BB * GG / 4);
    {
        dim3 g(GG / 256, 64);
        weff_kernel<<<g, 256>>>(geneW, geneb, termW, termb, whi, wlo, beff);
    }

    // 1) fused gene+term0 GEMM -> tanh z level0 + partial BN stats (64 slices)
    {
        cudaFuncSetAttribute(gemm_fused_kernel,
                             cudaFuncAttributeMaxDynamicSharedMemorySize, GEMM_SMEM);
        dim3 grid(NF2 / 64, BB / 64);
        gemm_fused_kernel<<<grid, 128, GEMM_SMEM>>>(xhi, xlo, whi, wlo, beff, h0);
    }

    // 2) level0: finalize stats (warp-parallel), then BN + aux
    stats2_kernel<<<(384 + 7) / 8, 256>>>(384, 64);
    {
        dim3 gterm(BB / 256, 64);
        bnaux_kernel<<<gterm, 256>>>(h0, bng, bnb, a1W, a1b, a2W, a2b, 0, 64, 0, out);
    }

    // 3) levels 1-3: term (+16-slice partials), finalize, bnaux
    const int   lvl_n[3]        = {16, 4, 1};
    const int   lvl_off[3]      = {64, 80, 84};
    const int   lvl_inStride[3] = {384, 96, 24};
    const float* lvl_in[3]      = {h0, h1, h2};
    float*      lvl_z[3]        = {h1, h2, h3};

    for (int l = 0; l < 3; l++) {
        const int n = lvl_n[l], off = lvl_off[l];
        dim3 gterm(BB / 256, n);
        term_kernel<<<gterm, 256>>>(lvl_in[l], lvl_inStride[l], termW, termb, off, n, lvl_z[l]);
        stats2_kernel<<<(n * 6 + 7) / 8, 256>>>(n * 6, 16);
        bnaux_kernel<<<gterm, 256>>>(lvl_z[l], bng, bnb, a1W, a1b, a2W, a2b,
                                     off, n, off, out);
    }

    // 4) final head
    final1_kernel<<<BB / 256, 256>>>(finalW, finalb);
    stats2_kernel<<<1, 256>>>(6, 16);
    final2_kernel<<<BB / 256, 256>>>(fbng, fbnb, fauxW, fauxb, foutW, foutb, out);
}

// round 15
// speedup vs baseline: 2.0608x; 1.1704x over previous
#include <cuda_runtime.h>
#include <cuda_bf16.h>
#include <math.h>
#include <stdint.h>

// Problem constants
#define BB   4096
#define GG   4096
#define NF2  384               // fused gene+term0 output width (64 terms x 6)
#define OUTC 86
#define EPSB 1e-5f
#define PSLI 64                // max partial-stat slices

// ---------------- scratch (device globals) ---------------------------------
__device__ __align__(16) float g_h0[BB * 384];
__device__ __align__(16) float g_h1[BB * 96];
__device__ __align__(16) float g_h2[BB * 24];
__device__ __align__(16) float g_h3[BB * 6];
__device__ __align__(16) float g_f [BB * 6];
__device__ float g_mean[512];
__device__ float g_var [512];
__device__ float g_psum[PSLI * 512];
__device__ float g_psq [PSLI * 512];
__device__ __align__(16) __nv_bfloat16 g_xhi[BB * GG];
__device__ __align__(16) __nv_bfloat16 g_xlo[BB * GG];
__device__ __align__(16) __nv_bfloat16 g_weffhi[NF2 * GG];
__device__ __align__(16) __nv_bfloat16 g_wefflo[NF2 * GG];
__device__ float g_beff[NF2];

// ======================= helpers ===========================================
__device__ __forceinline__ uint32_t smem_u32(const void* p) {
    uint32_t a;
    asm("{ .reg .u64 t; cvta.to.shared.u64 t, %1; cvt.u32.u64 %0, t; }" : "=r"(a) : "l"(p));
    return a;
}
#define CPA16(dst, src) \
    asm volatile("cp.async.cg.shared.global [%0], [%1], 16;" :: "r"(dst), "l"(src))
#define CPA_COMMIT() asm volatile("cp.async.commit_group;" ::: "memory")

#define LDSM4(r, addr) \
    asm volatile("ldmatrix.sync.aligned.m8n8.x4.shared.b16 {%0,%1,%2,%3}, [%4];" \
                 : "=r"((r)[0]), "=r"((r)[1]), "=r"((r)[2]), "=r"((r)[3]) : "r"(addr))

__device__ __forceinline__ void mma_bf16(float* d, const uint32_t* a, const uint32_t* b) {
    asm volatile(
        "mma.sync.aligned.m16n8k16.row.col.f32.bf16.bf16.f32 "
        "{%0,%1,%2,%3}, {%4,%5,%6,%7}, {%8,%9}, {%0,%1,%2,%3};"
        : "+f"(d[0]), "+f"(d[1]), "+f"(d[2]), "+f"(d[3])
        : "r"(a[0]), "r"(a[1]), "r"(a[2]), "r"(a[3]), "r"(b[0]), "r"(b[1]));
}

// ======================= fp32 -> bf16 hi/lo split ==========================
__global__ void __launch_bounds__(256)
split_kernel(const float* __restrict__ src, __nv_bfloat16* __restrict__ hi,
             __nv_bfloat16* __restrict__ lo, int n4) {
    int i = blockIdx.x * blockDim.x + threadIdx.x;
    if (i >= n4) return;
    float4 v = ((const float4*)src)[i];
    __nv_bfloat16 h0 = __float2bfloat16(v.x), h1 = __float2bfloat16(v.y);
    __nv_bfloat16 h2 = __float2bfloat16(v.z), h3 = __float2bfloat16(v.w);
    __nv_bfloat16 l0 = __float2bfloat16(v.x - __bfloat162float(h0));
    __nv_bfloat16 l1 = __float2bfloat16(v.y - __bfloat162float(h1));
    __nv_bfloat16 l2 = __float2bfloat16(v.z - __bfloat162float(h2));
    __nv_bfloat16 l3 = __float2bfloat16(v.w - __bfloat162float(h3));
    ((__nv_bfloat162*)hi)[i * 2 + 0] = __nv_bfloat162{h0, h1};
    ((__nv_bfloat162*)hi)[i * 2 + 1] = __nv_bfloat162{h2, h3};
    ((__nv_bfloat162*)lo)[i * 2 + 0] = __nv_bfloat162{l0, l1};
    ((__nv_bfloat162*)lo)[i * 2 + 1] = __nv_bfloat162{l2, l3};
}

// ======================= W_eff precompute ==================================
__global__ void __launch_bounds__(256)
weff_kernel(const float* __restrict__ geneW, const float* __restrict__ geneb,
            const float* __restrict__ termW, const float* __restrict__ termb,
            __nv_bfloat16* __restrict__ whi, __nv_bfloat16* __restrict__ wlo,
            float* __restrict__ beff) {
    const int t = blockIdx.y;
    __shared__ float tw[144];
    if (threadIdx.x < 144) tw[threadIdx.x] = termW[(size_t)t * 144 + threadIdx.x];
    __syncthreads();
    const int g = blockIdx.x * 256 + threadIdx.x;
    float gw[24];
#pragma unroll
    for (int k = 0; k < 24; k++) gw[k] = geneW[((size_t)t * 24 + k) * GG + g];
#pragma unroll
    for (int h = 0; h < 6; h++) {
        float s = 0.0f;
#pragma unroll
        for (int k = 0; k < 24; k++) s = fmaf(tw[h * 24 + k], gw[k], s);
        __nv_bfloat16 hi = __float2bfloat16(s);
        float lo = s - __bfloat162float(hi);
        whi[((size_t)(t * 6 + h)) * GG + g] = hi;
        wlo[((size_t)(t * 6 + h)) * GG + g] = __float2bfloat16(lo);
    }
    if (blockIdx.x == 0 && threadIdx.x < 6) {
        const int h = threadIdx.x;
        float s = termb[t * 6 + h];
#pragma unroll
        for (int k = 0; k < 24; k++) s = fmaf(tw[h * 24 + k], geneb[t * 24 + k], s);
        beff[t * 6 + h] = s;
    }
}

// ======================= fused bf16 GEMM + tanh + partial BN stats =========
#define KCH     64
#define NCHUNK  (GG / KCH)        // 64
#define A_HI_O  0
#define A_LO_O  8192
#define B_HI_O  16384
#define B_LO_O  24576
#define STAGE_B 32768             // 32KB
#define GEMM_SMEM (2 * STAGE_B)   // 64KB

__global__ void __launch_bounds__(128, 3)
gemm_fused_kernel(const __nv_bfloat16* __restrict__ Ahi, const __nv_bfloat16* __restrict__ Alo,
                  const __nv_bfloat16* __restrict__ Bhi, const __nv_bfloat16* __restrict__ Blo,
                  const float* __restrict__ beff, float* __restrict__ Z) {
    extern __shared__ __align__(128) char smem[];
    const uint32_t sb = smem_u32(smem);
    const int tid  = threadIdx.x;
    const int wid  = tid >> 5, lane = tid & 31;
    const int wm   = wid & 1;
    const int wn   = wid >> 1;
    const int m0   = blockIdx.y * 64, n0 = blockIdx.x * 64;

    const __nv_bfloat16* pA0 = Ahi + (size_t)m0 * GG;
    const __nv_bfloat16* pA1 = Alo + (size_t)m0 * GG;
    const __nv_bfloat16* pB0 = Bhi + (size_t)n0 * GG;
    const __nv_bfloat16* pB1 = Blo + (size_t)n0 * GG;

    float acc[2][4][4];
#pragma unroll
    for (int i = 0; i < 2; i++)
#pragma unroll
        for (int j = 0; j < 4; j++)
#pragma unroll
            for (int r = 0; r < 4; r++) acc[i][j][r] = 0.0f;

    const uint32_t aRowO = (uint32_t)(wm * 32 + (lane & 15)) * 128;
    const uint32_t aXor  = lane & 7;
    const uint32_t aHalf = (uint32_t)(lane >> 4);
    const uint32_t bRowO = (uint32_t)(wn * 32 + (lane & 7) + ((lane >> 4) << 3)) * 128;
    const uint32_t bXor  = lane & 7;
    const uint32_t bHalf = (uint32_t)((lane >> 3) & 1);

    auto load_chunk = [&](int u, int s) {
        const uint32_t stb = sb + (uint32_t)s * STAGE_B;
        const size_t kof = (size_t)u * KCH;
#pragma unroll
        for (int j = 0; j < 4; ++j) {
            const int idx = tid + j * 128;
            const int row = idx >> 3, ch = idx & 7;
            const uint32_t so = (uint32_t)row * 128 + (uint32_t)((ch ^ (row & 7)) << 4);
            const size_t go = (size_t)row * GG + kof + (size_t)ch * 8;
            CPA16(stb + A_HI_O + so, pA0 + go);
            CPA16(stb + A_LO_O + so, pA1 + go);
            CPA16(stb + B_HI_O + so, pB0 + go);
            CPA16(stb + B_LO_O + so, pB1 + go);
        }
        CPA_COMMIT();
    };

    load_chunk(0, 0);

    for (int t = 0; t < NCHUNK; ++t) {
        if (t + 1 < NCHUNK) {
            load_chunk(t + 1, (t + 1) & 1);
            asm volatile("cp.async.wait_group 1;" ::: "memory");
        } else {
            asm volatile("cp.async.wait_group 0;" ::: "memory");
        }
        __syncthreads();

        const uint32_t stb = sb + (uint32_t)(t & 1) * STAGE_B;
        const uint32_t aHiB = stb + A_HI_O + aRowO;
        const uint32_t aLoB = stb + A_LO_O + aRowO;
        const uint32_t bHiB = stb + B_HI_O + bRowO;
        const uint32_t bLoB = stb + B_LO_O + bRowO;

#pragma unroll
        for (int ks = 0; ks < 4; ++ks) {
            uint32_t ah[2][4], al[2][4], bh[2][4], bl[2][4];
            const uint32_t asw = (((2u * ks + aHalf) ^ aXor) << 4);
            const uint32_t bsw = (((2u * ks + bHalf) ^ bXor) << 4);
#pragma unroll
            for (int mi = 0; mi < 2; ++mi) {
                LDSM4(ah[mi], aHiB + (uint32_t)mi * 2048 + asw);
                LDSM4(al[mi], aLoB + (uint32_t)mi * 2048 + asw);
            }
#pragma unroll
            for (int p = 0; p < 2; ++p) {
                LDSM4(bh[p], bHiB + (uint32_t)p * 2048 + bsw);
                LDSM4(bl[p], bLoB + (uint32_t)p * 2048 + bsw);
            }
#pragma unroll
            for (int mi = 0; mi < 2; ++mi)
#pragma unroll
                for (int p = 0; p < 2; ++p)
#pragma unroll
                    for (int q = 0; q < 2; ++q) {
                        const int ni = p * 2 + q;
                        mma_bf16(acc[mi][ni], ah[mi], &bh[p][q * 2]);
                        mma_bf16(acc[mi][ni], ah[mi], &bl[p][q * 2]);
                        mma_bf16(acc[mi][ni], al[mi], &bh[p][q * 2]);
                    }
        }
        __syncthreads();
    }

    // epilogue: tanh(acc + beff) -> Z, plus per-CTA column partial sums
    const int rbase = m0 + wm * 32 + (lane >> 2);
    const int cbase = n0 + wn * 32 + (lane & 3) * 2;
    float cs[4][2], cq[4][2];
#pragma unroll
    for (int ni = 0; ni < 4; ++ni) { cs[ni][0] = cs[ni][1] = cq[ni][0] = cq[ni][1] = 0.0f; }

#pragma unroll
    for (int mi = 0; mi < 2; ++mi) {
#pragma unroll
        for (int ni = 0; ni < 4; ++ni) {
            const int col = cbase + ni * 8;
            const float b0 = __ldg(&beff[col]), b1 = __ldg(&beff[col + 1]);
            const int r0 = rbase + mi * 16;
            float t00 = tanhf(acc[mi][ni][0] + b0);
            float t01 = tanhf(acc[mi][ni][1] + b1);
            float t10 = tanhf(acc[mi][ni][2] + b0);
            float t11 = tanhf(acc[mi][ni][3] + b1);
            *(float2*)&Z[(size_t)r0 * NF2 + col]       = make_float2(t00, t01);
            *(float2*)&Z[(size_t)(r0 + 8) * NF2 + col] = make_float2(t10, t11);
            cs[ni][0] += t00 + t10; cq[ni][0] += t00 * t00 + t10 * t10;
            cs[ni][1] += t01 + t11; cq[ni][1] += t01 * t01 + t11 * t11;
        }
    }
#pragma unroll
    for (int off = 4; off <= 16; off <<= 1) {
#pragma unroll
        for (int ni = 0; ni < 4; ++ni) {
#pragma unroll
            for (int p = 0; p < 2; ++p) {
                cs[ni][p] += __shfl_down_sync(0xffffffffu, cs[ni][p], off);
                cq[ni][p] += __shfl_down_sync(0xffffffffu, cq[ni][p], off);
            }
        }
    }
    float* sred = (float*)smem;   // reuse pipeline smem (loads complete)
    if (lane < 4) {
#pragma unroll
        for (int ni = 0; ni < 4; ++ni) {
#pragma unroll
            for (int p = 0; p < 2; ++p) {
                const int cl = wn * 32 + lane * 2 + ni * 8 + p;
                sred[wm * 128 + cl]      = cs[ni][p];
                sred[wm * 128 + 64 + cl] = cq[ni][p];
            }
        }
    }
    __syncthreads();
    if (tid < 64) {
        g_psum[blockIdx.y * 512 + n0 + tid] = sred[tid]      + sred[128 + tid];
        g_psq [blockIdx.y * 512 + n0 + tid] = sred[64 + tid] + sred[192 + tid];
    }
}

// ======================= stats finalize (warp-parallel slices) =============
__global__ void __launch_bounds__(256)
stats2_kernel(int C, int nsli) {
    const int lane = threadIdx.x & 31;
    const int ch   = threadIdx.x >> 5;
    const int c    = blockIdx.x * 8 + ch;
    if (c >= C) return;
    double s = 0.0, q = 0.0;
    if (lane < nsli) {
        s = (double)g_psum[lane * 512 + c];
        q = (double)g_psq [lane * 512 + c];
    }
    if (lane + 32 < nsli) {
        s += (double)g_psum[(lane + 32) * 512 + c];
        q += (double)g_psq [(lane + 32) * 512 + c];
    }
#pragma unroll
    for (int off = 16; off > 0; off >>= 1) {
        s += __shfl_down_sync(0xffffffffu, s, off);
        q += __shfl_down_sync(0xffffffffu, q, off);
    }
    if (lane == 0) {
        float mu = (float)(s / (double)BB);
        g_mean[c] = mu;
        g_var[c]  = (float)(q / (double)BB - (double)mu * (double)mu);
    }
}

// ======================= fused BN(l) + aux(l) + term(l+1) ==================
// Block y = next-level term tn; parents = level-l terms 4tn..4tn+3 (24 ch).
// Normalizes in registers (never writes h), emits 4 aux columns, computes
// next-level z (+tanh) and 16-slice stats partials.
__global__ void __launch_bounds__(256)
fused_bn_term_kernel(const float* __restrict__ zin, int n_l, int off_l,
                     const float* __restrict__ gamma, const float* __restrict__ beta,
                     const float* __restrict__ a1W, const float* __restrict__ a1b,
                     const float* __restrict__ a2W, const float* __restrict__ a2b,
                     const float* __restrict__ termW, const float* __restrict__ termb,
                     float* __restrict__ zout, float* __restrict__ out) {
    const int tn = blockIdx.y;
    const int off_next = off_l + n_l;
    const int wid = threadIdx.x >> 5, lane = threadIdx.x & 31;
    __shared__ float snrm[24], sb24[24], sa1W[24];   // snrm = rsqrt(var)*gamma
    __shared__ float smu[24];
    __shared__ float sa1b[4], sa2W[4], sa2b[4];
    __shared__ float tW[144], tb[6];
    __shared__ float rs[8][6], rq[8][6];
    if (threadIdx.x < 24) {
        const int c = tn * 24 + threadIdx.x;           // channel in level l
        smu[threadIdx.x]  = g_mean[c];
        snrm[threadIdx.x] = rsqrtf(g_var[c] + EPSB) * gamma[off_l * 6 + c];
        sb24[threadIdx.x] = beta[off_l * 6 + c];
        sa1W[threadIdx.x] = a1W[off_l * 6 + c];
    } else if (threadIdx.x >= 32 && threadIdx.x < 36) {
        const int p = threadIdx.x - 32;
        sa1b[p] = a1b[off_l + tn * 4 + p];
        sa2W[p] = a2W[off_l + tn * 4 + p];
        sa2b[p] = a2b[off_l + tn * 4 + p];
    } else if (threadIdx.x >= 64 && threadIdx.x < 208) {
        tW[threadIdx.x - 64] = termW[(size_t)(off_next + tn) * 144 + threadIdx.x - 64];
    } else if (threadIdx.x >= 224 && threadIdx.x < 230) {
        tb[threadIdx.x - 224] = termb[(size_t)(off_next + tn) * 6 + threadIdx.x - 224];
    }
    __syncthreads();

    const int b = blockIdx.x * blockDim.x + threadIdx.x;
    const int C = n_l * 6;
    float hv[24];
    const float* ip = zin + (size_t)b * C + tn * 24;
#pragma unroll
    for (int i = 0; i < 24; i += 4) {
        float4 v = *(const float4*)&ip[i];
        hv[i + 0] = (v.x - smu[i + 0]) * snrm[i + 0] + sb24[i + 0];
        hv[i + 1] = (v.y - smu[i + 1]) * snrm[i + 1] + sb24[i + 1];
        hv[i + 2] = (v.z - smu[i + 2]) * snrm[i + 2] + sb24[i + 2];
        hv[i + 3] = (v.w - smu[i + 3]) * snrm[i + 3] + sb24[i + 3];
    }
    // aux heads for 4 parent terms
#pragma unroll
    for (int p = 0; p < 4; ++p) {
        float a = sa1b[p];
#pragma unroll
        for (int k = 0; k < 6; ++k) a = fmaf(hv[p * 6 + k], sa1W[p * 6 + k], a);
        out[(size_t)b * OUTC + off_l + tn * 4 + p] = fmaf(tanhf(a), sa2W[p], sa2b[p]);
    }
    // next-level term
    const int Cn = (n_l / 4) * 6;
    float s6[6], q6[6];
#pragma unroll
    for (int h = 0; h < 6; ++h) {
        float s = tb[h];
#pragma unroll
        for (int i = 0; i < 24; ++i) s = fmaf(hv[i], tW[h * 24 + i], s);
        float tv = tanhf(s);
        zout[(size_t)b * Cn + tn * 6 + h] = tv;
        s6[h] = tv; q6[h] = tv * tv;
    }
#pragma unroll
    for (int offx = 16; offx > 0; offx >>= 1) {
#pragma unroll
        for (int h = 0; h < 6; ++h) {
            s6[h] += __shfl_down_sync(0xffffffffu, s6[h], offx);
            q6[h] += __shfl_down_sync(0xffffffffu, q6[h], offx);
        }
    }
    if (lane == 0) {
#pragma unroll
        for (int h = 0; h < 6; ++h) { rs[wid][h] = s6[h]; rq[wid][h] = q6[h]; }
    }
    __syncthreads();
    if (threadIdx.x < 6) {
        float s = 0.0f, q = 0.0f;
#pragma unroll
        for (int w = 0; w < 8; ++w) { s += rs[w][threadIdx.x]; q += rq[w][threadIdx.x]; }
        g_psum[blockIdx.x * 512 + tn * 6 + threadIdx.x] = s;
        g_psq [blockIdx.x * 512 + tn * 6 + threadIdx.x] = q;
    }
}

// ======================= final head ========================================
// BN of level-3 z (6 ch) + aux col 84 + f = tanh(h @ fW^T + fb) + partials
__global__ void __launch_bounds__(256)
final1_kernel(const float* __restrict__ gamma, const float* __restrict__ beta,
              const float* __restrict__ a1W, const float* __restrict__ a1b,
              const float* __restrict__ a2W, const float* __restrict__ a2b,
              const float* __restrict__ fW, const float* __restrict__ fb,
              float* __restrict__ out) {
    const int wid = threadIdx.x >> 5, lane = threadIdx.x & 31;
    __shared__ float smu[6], snrm[6], sb6[6], sa1W6[6], sfW[36], sfb[6];
    __shared__ float rs[8][6], rq[8][6];
    if (threadIdx.x < 6) {
        smu[threadIdx.x]  = g_mean[threadIdx.x];
        snrm[threadIdx.x] = rsqrtf(g_var[threadIdx.x] + EPSB) * gamma[84 * 6 + threadIdx.x];
        sb6[threadIdx.x]  = beta[84 * 6 + threadIdx.x];
        sa1W6[threadIdx.x] = a1W[84 * 6 + threadIdx.x];
        sfb[threadIdx.x]  = fb[threadIdx.x];
    } else if (threadIdx.x >= 32 && threadIdx.x < 68) {
        sfW[threadIdx.x - 32] = fW[threadIdx.x - 32];
    }
    __syncthreads();
    const int b = blockIdx.x * blockDim.x + threadIdx.x;
    float hv[6];
#pragma unroll
    for (int i = 0; i < 6; ++i)
        hv[i] = (g_h3[(size_t)b * 6 + i] - smu[i]) * snrm[i] + sb6[i];
    {
        float a = a1b[84];
#pragma unroll
        for (int k = 0; k < 6; ++k) a = fmaf(hv[k], sa1W6[k], a);
        out[(size_t)b * OUTC + 84] = fmaf(tanhf(a), a2W[84], a2b[84]);
    }
    float s6[6], q6[6];
#pragma unroll
    for (int o = 0; o < 6; ++o) {
        float s = sfb[o];
#pragma unroll
        for (int i = 0; i < 6; ++i) s = fmaf(hv[i], sfW[o * 6 + i], s);
        float tv = tanhf(s);
        g_f[(size_t)b * 6 + o] = tv;
        s6[o] = tv; q6[o] = tv * tv;
    }
#pragma unroll
    for (int offx = 16; offx > 0; offx >>= 1) {
#pragma unroll
        for (int h = 0; h < 6; ++h) {
            s6[h] += __shfl_down_sync(0xffffffffu, s6[h], offx);
            q6[h] += __shfl_down_sync(0xffffffffu, q6[h], offx);
        }
    }
    if (lane == 0) {
#pragma unroll
        for (int h = 0; h < 6; ++h) { rs[wid][h] = s6[h]; rq[wid][h] = q6[h]; }
    }
    __syncthreads();
    if (threadIdx.x < 6) {
        float s = 0.0f, q = 0.0f;
#pragma unroll
        for (int w = 0; w < 8; ++w) { s += rs[w][threadIdx.x]; q += rq[w][threadIdx.x]; }
        g_psum[blockIdx.x * 512 + threadIdx.x] = s;
        g_psq [blockIdx.x * 512 + threadIdx.x] = q;
    }
}

__global__ void __launch_bounds__(256)
final2_kernel(const float* __restrict__ fg, const float* __restrict__ fbta,
              const float* __restrict__ fauxW, const float* __restrict__ fauxb,
              const float* __restrict__ foutW, const float* __restrict__ foutb,
              float* __restrict__ out) {
    const int b = blockIdx.x * blockDim.x + threadIdx.x;
    float a = fauxb[0];
#pragma unroll
    for (int h = 0; h < 6; h++) {
        float v = (g_f[(size_t)b * 6 + h] - g_mean[h]) * rsqrtf(g_var[h] + EPSB) * fg[h] + fbta[h];
        a = fmaf(v, fauxW[h], a);
    }
    float fa = tanhf(a);
    float p = fmaf(fa, foutW[0], foutb[0]);
    out[(size_t)b * OUTC + 85] = 1.0f / (1.0f + expf(-p));
}

// ---------------------------------------------------------------------------
extern "C" void kernel_launch(void* const* d_in, const int* in_sizes, int n_in,
                              void* d_out, int out_size) {
    (void)in_sizes; (void)n_in; (void)out_size;
    const float* x      = (const float*)d_in[0];
    const float* geneW  = (const float*)d_in[1];
    const float* geneb  = (const float*)d_in[2];
    const float* termW  = (const float*)d_in[3];
    const float* termb  = (const float*)d_in[4];
    const float* bng    = (const float*)d_in[5];
    const float* bnb    = (const float*)d_in[6];
    const float* a1W    = (const float*)d_in[7];
    const float* a1b    = (const float*)d_in[8];
    const float* a2W    = (const float*)d_in[9];
    const float* a2b    = (const float*)d_in[10];
    const float* finalW = (const float*)d_in[11];
    const float* finalb = (const float*)d_in[12];
    const float* fbng   = (const float*)d_in[13];
    const float* fbnb   = (const float*)d_in[14];
    const float* fauxW  = (const float*)d_in[15];
    const float* fauxb  = (const float*)d_in[16];
    const float* foutW  = (const float*)d_in[17];
    const float* foutb  = (const float*)d_in[18];
    float* out = (float*)d_out;

    float *h0, *h1, *h2, *h3, *beff;
    __nv_bfloat16 *xhi, *xlo, *whi, *wlo;
    cudaGetSymbolAddress((void**)&h0, g_h0);
    cudaGetSymbolAddress((void**)&h1, g_h1);
    cudaGetSymbolAddress((void**)&h2, g_h2);
    cudaGetSymbolAddress((void**)&h3, g_h3);
    cudaGetSymbolAddress((void**)&xhi, g_xhi);
    cudaGetSymbolAddress((void**)&xlo, g_xlo);
    cudaGetSymbolAddress((void**)&whi, g_weffhi);
    cudaGetSymbolAddress((void**)&wlo, g_wefflo);
    cudaGetSymbolAddress((void**)&beff, g_beff);

    // 0) x split + W_eff precompute
    split_kernel<<<(BB * GG / 4 + 255) / 256, 256>>>(x, xhi, xlo, BB * GG / 4);
    {
        dim3 g(GG / 256, 64);
        weff_kernel<<<g, 256>>>(geneW, geneb, termW, termb, whi, wlo, beff);
    }

    // 1) fused gene+term0 GEMM -> tanh z level0 + partial BN stats (64 slices)
    {
        cudaFuncSetAttribute(gemm_fused_kernel,
                             cudaFuncAttributeMaxDynamicSharedMemorySize, GEMM_SMEM);
        dim3 grid(NF2 / 64, BB / 64);
        gemm_fused_kernel<<<grid, 128, GEMM_SMEM>>>(xhi, xlo, whi, wlo, beff, h0);
    }

    // 2) chained BN+aux+term fusions
    stats2_kernel<<<(384 + 7) / 8, 256>>>(384, 64);
    {   // level0 -> level1
        dim3 g(BB / 256, 16);
        fused_bn_term_kernel<<<g, 256>>>(h0, 64, 0, bng, bnb, a1W, a1b, a2W, a2b,
                                         termW, termb, h1, out);
    }
    stats2_kernel<<<(96 + 7) / 8, 256>>>(96, 16);
    {   // level1 -> level2
        dim3 g(BB / 256, 4);
        fused_bn_term_kernel<<<g, 256>>>(h1, 16, 64, bng, bnb, a1W, a1b, a2W, a2b,
                                         termW, termb, h2, out);
    }
    stats2_kernel<<<(24 + 7) / 8, 256>>>(24, 16);
    {   // level2 -> level3
        dim3 g(BB / 256, 1);
        fused_bn_term_kernel<<<g, 256>>>(h2, 4, 80, bng, bnb, a1W, a1b, a2W, a2b,
                                         termW, termb, h3, out);
    }
    stats2_kernel<<<1, 256>>>(6, 16);

    // 3) final head: BN level3 + aux col84 + f (+partials), stats, output
    final1_kernel<<<BB / 256, 256>>>(bng, bnb, a1W, a1b, a2W, a2b, finalW, finalb, out);
    stats2_kernel<<<1, 256>>>(6, 16);
    final2_kernel<<<BB / 256, 256>>>(fbng, fbnb, fauxW, fauxb, foutW, foutb, out);
}